// round 2
// baseline (speedup 1.0000x reference)
#include <cuda_runtime.h>
#include <math.h>

// Problem constants
#define NN 4096
#define DD 512
#define REGC 1.0f
#define INV_REG_LN2 1.4426950408889634f   // 1/(REG*ln2)
#define REG_LN2     0.6931471805599453f   // REG*ln2
#define LOG_A       (-8.317766166719343f) // -log(4096)
#define SUM_LAB     (-16.635532333438686f) // log_a + log_b

// Scratch (device globals; no allocations allowed)
__device__ float d_M[(size_t)NN * NN];   // 64MB cost matrix, L2-resident
__device__ float d_f[NN], d_fs[NN];      // f and f/(REG*ln2)
__device__ float d_g[NN], d_gs[NN];
__device__ float d_x2[NN], d_y2[NN];
__device__ double d_acc[3];              // S1, S2, S3

__device__ __forceinline__ float ex2f_(float x) {
    float y; asm("ex2.approx.ftz.f32 %0, %1;" : "=f"(y) : "f"(x)); return y;
}
__device__ __forceinline__ float lg2f_(float x) {
    float y; asm("lg2.approx.f32 %0, %1;" : "=f"(y) : "f"(x)); return y;
}
__device__ __forceinline__ float neg_inf_() { return __int_as_float(0xff800000); }

// ---------------------------------------------------------------------------
__global__ void init_kernel() {
    int t = blockIdx.x * blockDim.x + threadIdx.x;
    if (t < 3) d_acc[t] = 0.0;
    if (t < NN) { d_g[t] = 0.f; d_gs[t] = 0.f; d_f[t] = 0.f; d_fs[t] = 0.f; }
}

// One block per row (8192 rows total: first 4096 = source, rest = target)
__global__ void norms_kernel(const float* __restrict__ X, const float* __restrict__ Y) {
    int row = blockIdx.x;
    const float* p = (row < NN) ? (X + (size_t)row * DD) : (Y + (size_t)(row - NN) * DD);
    int t = threadIdx.x;  // 128 threads, 4 floats each via float4
    float4 v = ((const float4*)p)[t];
    float s = v.x * v.x + v.y * v.y + v.z * v.z + v.w * v.w;
    #pragma unroll
    for (int o = 16; o; o >>= 1) s += __shfl_down_sync(0xffffffffu, s, o);
    __shared__ float sm[4];
    if ((t & 31) == 0) sm[t >> 5] = s;
    __syncthreads();
    if (t == 0) {
        float r = sm[0] + sm[1] + sm[2] + sm[3];
        if (row < NN) d_x2[row] = r; else d_y2[row - NN] = r;
    }
}

// ---------------------------------------------------------------------------
// SGEMM: M[i][j] = max(x2[i] + y2[j] - 2 * dot(X_i, Y_j), 0)
#define BM 128
#define BN 128
#define BK 8
__global__ void __launch_bounds__(256, 2) gemm_kernel(const float* __restrict__ X,
                                                      const float* __restrict__ Y) {
    __shared__ float As[BK][BM];
    __shared__ float Bs[BK][BN];
    int tid = threadIdx.x;
    int tx = tid & 15, ty = tid >> 4;
    int bx = blockIdx.x, by = blockIdx.y;

    int mloc = tid >> 1;              // 0..127
    int kq = (tid & 1) * 4;           // 0 or 4
    const float* pA = X + (size_t)(by * BM + mloc) * DD + kq;
    const float* pB = Y + (size_t)(bx * BN + mloc) * DD + kq;

    float acc[8][8];
    #pragma unroll
    for (int i = 0; i < 8; i++)
        #pragma unroll
        for (int j = 0; j < 8; j++) acc[i][j] = 0.f;

    float4 a4 = *(const float4*)pA;
    float4 b4 = *(const float4*)pB;

    const int NKT = DD / BK; // 64
    for (int kt = 0; kt < NKT; kt++) {
        As[kq + 0][mloc] = a4.x; As[kq + 1][mloc] = a4.y;
        As[kq + 2][mloc] = a4.z; As[kq + 3][mloc] = a4.w;
        Bs[kq + 0][mloc] = b4.x; Bs[kq + 1][mloc] = b4.y;
        Bs[kq + 2][mloc] = b4.z; Bs[kq + 3][mloc] = b4.w;
        __syncthreads();
        if (kt + 1 < NKT) {
            a4 = *(const float4*)(pA + (kt + 1) * BK);
            b4 = *(const float4*)(pB + (kt + 1) * BK);
        }
        #pragma unroll
        for (int k = 0; k < BK; k++) {
            float a[8], b[8];
            *(float4*)(&a[0]) = *(const float4*)(&As[k][ty * 8]);
            *(float4*)(&a[4]) = *(const float4*)(&As[k][ty * 8 + 4]);
            *(float4*)(&b[0]) = *(const float4*)(&Bs[k][tx * 8]);
            *(float4*)(&b[4]) = *(const float4*)(&Bs[k][tx * 8 + 4]);
            #pragma unroll
            for (int i = 0; i < 8; i++)
                #pragma unroll
                for (int j = 0; j < 8; j++)
                    acc[i][j] = fmaf(a[i], b[j], acc[i][j]);
        }
        __syncthreads();
    }

    int r0 = by * BM + ty * 8;
    int c0 = bx * BN + tx * 8;
    float y2v[8];
    #pragma unroll
    for (int j = 0; j < 8; j++) y2v[j] = d_y2[c0 + j];
    #pragma unroll
    for (int i = 0; i < 8; i++) {
        float x2v = d_x2[r0 + i];
        float out[8];
        #pragma unroll
        for (int j = 0; j < 8; j++)
            out[j] = fmaxf(x2v + y2v[j] - 2.f * acc[i][j], 0.f);
        float* dst = d_M + (size_t)(r0 + i) * NN + c0;
        *(float4*)(dst)     = *(float4*)(&out[0]);
        *(float4*)(dst + 4) = *(float4*)(&out[4]);
    }
}

// ---------------------------------------------------------------------------
// Streaming (online) LSE helpers: single EX2 per element
__device__ __forceinline__ void lse_accum(float x, float& m, float& s) {
    float dd = x - m;
    float e = ex2f_(0.f - fabsf(dd));
    if (dd > 0.f) { s = fmaf(s, e, 1.f); m = x; }
    else          { s += e; }
}
__device__ __forceinline__ void lse_combine(float mo, float so, float& m, float& s) {
    float mm = fmaxf(m, mo);
    s = s * ex2f_(m - mm) + so * ex2f_(mo - mm);
    m = mm;
}

// f update: f_i = REG*(log_a - lse_j((g_j - M_ij)/REG))
// grid 512 blocks x 256 threads; each block does 8 rows
__global__ void __launch_bounds__(256) f_kernel() {
    __shared__ float gs[NN];          // g / (REG*ln2)
    __shared__ float rm[8], rs[8];
    int t = threadIdx.x;
    for (int j = t; j < NN; j += 256) gs[j] = d_gs[j];
    __syncthreads();
    int row0 = blockIdx.x * 8;
    for (int r = 0; r < 8; r++) {
        const float* Mr = d_M + (size_t)(row0 + r) * NN;
        float m = neg_inf_(), s = 0.f;
        #pragma unroll 4
        for (int j = t; j < NN; j += 256) {
            float x = fmaf(Mr[j], -INV_REG_LN2, gs[j]);
            lse_accum(x, m, s);
        }
        #pragma unroll
        for (int o = 16; o; o >>= 1) {
            float mo = __shfl_down_sync(0xffffffffu, m, o);
            float so = __shfl_down_sync(0xffffffffu, s, o);
            lse_combine(mo, so, m, s);
        }
        if ((t & 31) == 0) { rm[t >> 5] = m; rs[t >> 5] = s; }
        __syncthreads();
        if (t < 32) {
            float m2 = (t < 8) ? rm[t] : neg_inf_();
            float s2 = (t < 8) ? rs[t] : 0.f;
            #pragma unroll
            for (int o = 4; o; o >>= 1) {
                float mo = __shfl_down_sync(0xffffffffu, m2, o);
                float so = __shfl_down_sync(0xffffffffu, s2, o);
                float mm = fmaxf(m2, mo);
                s2 = s2 * ex2f_(m2 - mm) + so * ex2f_(mo - mm);
                m2 = mm;
            }
            if (t == 0) {
                float lse2 = m2 + lg2f_(s2);
                float fv = REGC * LOG_A - REG_LN2 * lse2;
                d_f[row0 + r] = fv;
                d_fs[row0 + r] = fv * INV_REG_LN2;
            }
        }
        __syncthreads();
    }
}

// g update: g_j = REG*(log_b - lse_i((f_i - M_ij)/REG))
// grid 128 blocks x 1024 threads; block = 32-column slab, 32 row-groups
__global__ void __launch_bounds__(1024) g_kernel() {
    __shared__ float fs[NN];
    __shared__ float pm[32][33], ps[32][33];
    int t = threadIdx.x;
    for (int j = t; j < NN; j += 1024) fs[j] = d_fs[j];
    __syncthreads();
    int lane = t & 31;
    int rg = t >> 5;                  // 0..31
    int col = blockIdx.x * 32 + lane;
    const float* Mc = d_M + col;
    float m = neg_inf_(), s = 0.f;
    #pragma unroll 4
    for (int i = rg; i < NN; i += 32) {
        float x = fmaf(Mc[(size_t)i * NN], -INV_REG_LN2, fs[i]);
        lse_accum(x, m, s);
    }
    pm[rg][lane] = m; ps[rg][lane] = s;
    __syncthreads();
    // warp w reduces column w's 32 partials
    int w = t >> 5;
    float m2 = pm[lane][w];
    float s2 = ps[lane][w];
    #pragma unroll
    for (int o = 16; o; o >>= 1) {
        float mo = __shfl_down_sync(0xffffffffu, m2, o);
        float so = __shfl_down_sync(0xffffffffu, s2, o);
        float mm = fmaxf(m2, mo);
        s2 = s2 * ex2f_(m2 - mm) + so * ex2f_(mo - mm);
        m2 = mm;
    }
    if (lane == 0) {
        float lse2 = m2 + lg2f_(s2);
        float gv = REGC * LOG_A - REG_LN2 * lse2;   // log_b == log_a
        int c = blockIdx.x * 32 + w;
        d_g[c] = gv;
        d_gs[c] = gv * INV_REG_LN2;
    }
}

// Final reduction: S1 = sum P*M, S2 = sum P*logP, S3 = sum P
__global__ void __launch_bounds__(256) final_kernel() {
    __shared__ float gsh[NN];
    __shared__ float r1[8], r2[8], r3[8];
    int t = threadIdx.x;
    for (int j = t; j < NN; j += 256) gsh[j] = d_g[j];
    __syncthreads();
    int row0 = blockIdx.x * 8;
    float S1 = 0.f, S2 = 0.f, S3 = 0.f;
    for (int r = 0; r < 8; r++) {
        float fi = d_f[row0 + r];
        const float* Mr = d_M + (size_t)(row0 + r) * NN;
        #pragma unroll 4
        for (int j = t; j < NN; j += 256) {
            float Mv = Mr[j];
            float lp = (fi + gsh[j] - Mv) * (1.0f / REGC);
            float p = ex2f_(lp * 1.4426950408889634f);
            S1 = fmaf(p, Mv, S1);
            S2 = fmaf(p, lp, S2);
            S3 += p;
        }
    }
    #pragma unroll
    for (int o = 16; o; o >>= 1) {
        S1 += __shfl_down_sync(0xffffffffu, S1, o);
        S2 += __shfl_down_sync(0xffffffffu, S2, o);
        S3 += __shfl_down_sync(0xffffffffu, S3, o);
    }
    if ((t & 31) == 0) { r1[t >> 5] = S1; r2[t >> 5] = S2; r3[t >> 5] = S3; }
    __syncthreads();
    if (t == 0) {
        double a1 = 0, a2 = 0, a3 = 0;
        for (int w = 0; w < 8; w++) { a1 += r1[w]; a2 += r2[w]; a3 += r3[w]; }
        atomicAdd(&d_acc[0], a1);
        atomicAdd(&d_acc[1], a2);
        atomicAdd(&d_acc[2], a3);
    }
}

__global__ void finalize_kernel(float* out) {
    double S1 = d_acc[0], S2 = d_acc[1], S3 = d_acc[2];
    // value = S1 + REG*( S2 - (log_a+log_b)*S3 - S3 + 1 )
    double v = S1 + (double)REGC * (S2 - (double)SUM_LAB * S3 - S3 + 1.0);
    out[0] = (float)v;
}

// ---------------------------------------------------------------------------
extern "C" void kernel_launch(void* const* d_in, const int* in_sizes, int n_in,
                              void* d_out, int out_size) {
    const float* X = (const float*)d_in[0];   // source [4096,512]
    const float* Y = (const float*)d_in[1];   // target [4096,512]

    init_kernel<<<16, 256>>>();
    norms_kernel<<<2 * NN, 128>>>(X, Y);
    dim3 gg(NN / BN, NN / BM);
    gemm_kernel<<<gg, 256>>>(X, Y);
    for (int it = 0; it < 100; it++) {
        f_kernel<<<512, 256>>>();
        g_kernel<<<128, 1024>>>();
    }
    final_kernel<<<512, 256>>>();
    finalize_kernel<<<1, 1>>>((float*)d_out);
}

// round 3
// speedup vs baseline: 1.0638x; 1.0638x over previous
#include <cuda_runtime.h>
#include <math.h>

// Problem constants
#define NN 4096
#define DD 512
#define REGC 1.0f
#define INV_REG_LN2 1.4426950408889634f   // 1/(REG*ln2)
#define REG_LN2     0.6931471805599453f   // REG*ln2
#define LOG_A       (-8.317766166719343f) // -log(4096)
#define SUM_LAB     (-16.635532333438686f) // log_a + log_b

// Scratch (device globals; no allocations allowed)
__device__ float d_M[(size_t)NN * NN];   // 64MB cost matrix
__device__ float d_f[NN], d_fs[NN];      // f and f/(REG*ln2)
__device__ float d_g[NN], d_gs[NN];
__device__ float d_x2[NN], d_y2[NN];
__device__ double d_acc[3];              // S1, S2, S3

__device__ __forceinline__ float ex2f_(float x) {
    float y; asm("ex2.approx.ftz.f32 %0, %1;" : "=f"(y) : "f"(x)); return y;
}
__device__ __forceinline__ float lg2f_(float x) {
    float y; asm("lg2.approx.f32 %0, %1;" : "=f"(y) : "f"(x)); return y;
}
__device__ __forceinline__ float neg_inf_() { return __int_as_float(0xff800000); }

// Branchless streaming LSE step (base-2 domain): one MUFU per element
__device__ __forceinline__ void lse_accum(float x, float& m, float& s) {
    float d = x - m;
    float e = ex2f_(0.f - fabsf(d));
    bool gt = d > 0.f;
    s = fmaf(s, gt ? e : 1.f, gt ? 1.f : e);
    m = gt ? x : m;
}
__device__ __forceinline__ void lse_combine(float mo, float so, float& m, float& s) {
    float mm = fmaxf(m, mo);
    s = s * ex2f_(m - mm) + so * ex2f_(mo - mm);
    m = mm;
}

// ---------------------------------------------------------------------------
__global__ void init_kernel() {
    int t = blockIdx.x * blockDim.x + threadIdx.x;
    if (t < 3) d_acc[t] = 0.0;
    if (t < NN) { d_g[t] = 0.f; d_gs[t] = 0.f; d_f[t] = 0.f; d_fs[t] = 0.f; }
}

__global__ void norms_kernel(const float* __restrict__ X, const float* __restrict__ Y) {
    int row = blockIdx.x;
    const float* p = (row < NN) ? (X + (size_t)row * DD) : (Y + (size_t)(row - NN) * DD);
    int t = threadIdx.x;  // 128 threads, float4 each
    float4 v = ((const float4*)p)[t];
    float s = v.x * v.x + v.y * v.y + v.z * v.z + v.w * v.w;
    #pragma unroll
    for (int o = 16; o; o >>= 1) s += __shfl_down_sync(0xffffffffu, s, o);
    __shared__ float sm[4];
    if ((t & 31) == 0) sm[t >> 5] = s;
    __syncthreads();
    if (t == 0) {
        float r = sm[0] + sm[1] + sm[2] + sm[3];
        if (row < NN) d_x2[row] = r; else d_y2[row - NN] = r;
    }
}

// ---------------------------------------------------------------------------
// SGEMM: M[i][j] = max(x2[i] + y2[j] - 2 * dot(X_i, Y_j), 0)
#define BM 128
#define BN 128
#define BK 8
__global__ void __launch_bounds__(256, 2) gemm_kernel(const float* __restrict__ X,
                                                      const float* __restrict__ Y) {
    __shared__ float As[BK][BM];
    __shared__ float Bs[BK][BN];
    int tid = threadIdx.x;
    int tx = tid & 15, ty = tid >> 4;
    int bx = blockIdx.x, by = blockIdx.y;

    int mloc = tid >> 1;
    int kq = (tid & 1) * 4;
    const float* pA = X + (size_t)(by * BM + mloc) * DD + kq;
    const float* pB = Y + (size_t)(bx * BN + mloc) * DD + kq;

    float acc[8][8];
    #pragma unroll
    for (int i = 0; i < 8; i++)
        #pragma unroll
        for (int j = 0; j < 8; j++) acc[i][j] = 0.f;

    float4 a4 = *(const float4*)pA;
    float4 b4 = *(const float4*)pB;

    const int NKT = DD / BK;
    for (int kt = 0; kt < NKT; kt++) {
        As[kq + 0][mloc] = a4.x; As[kq + 1][mloc] = a4.y;
        As[kq + 2][mloc] = a4.z; As[kq + 3][mloc] = a4.w;
        Bs[kq + 0][mloc] = b4.x; Bs[kq + 1][mloc] = b4.y;
        Bs[kq + 2][mloc] = b4.z; Bs[kq + 3][mloc] = b4.w;
        __syncthreads();
        if (kt + 1 < NKT) {
            a4 = *(const float4*)(pA + (kt + 1) * BK);
            b4 = *(const float4*)(pB + (kt + 1) * BK);
        }
        #pragma unroll
        for (int k = 0; k < BK; k++) {
            float a[8], b[8];
            *(float4*)(&a[0]) = *(const float4*)(&As[k][ty * 8]);
            *(float4*)(&a[4]) = *(const float4*)(&As[k][ty * 8 + 4]);
            *(float4*)(&b[0]) = *(const float4*)(&Bs[k][tx * 8]);
            *(float4*)(&b[4]) = *(const float4*)(&Bs[k][tx * 8 + 4]);
            #pragma unroll
            for (int i = 0; i < 8; i++)
                #pragma unroll
                for (int j = 0; j < 8; j++)
                    acc[i][j] = fmaf(a[i], b[j], acc[i][j]);
        }
        __syncthreads();
    }

    int r0 = by * BM + ty * 8;
    int c0 = bx * BN + tx * 8;
    float y2v[8];
    #pragma unroll
    for (int j = 0; j < 8; j++) y2v[j] = d_y2[c0 + j];
    #pragma unroll
    for (int i = 0; i < 8; i++) {
        float x2v = d_x2[r0 + i];
        float out[8];
        #pragma unroll
        for (int j = 0; j < 8; j++)
            out[j] = fmaxf(x2v + y2v[j] - 2.f * acc[i][j], 0.f);
        float* dst = d_M + (size_t)(r0 + i) * NN + c0;
        *(float4*)(dst)     = *(float4*)(&out[0]);
        *(float4*)(dst + 4) = *(float4*)(&out[4]);
    }
}

// ---------------------------------------------------------------------------
// f update: f_i = REG*(log_a - lse_j((g_j - M_ij)/REG))
// grid 1024 blocks x 256 threads; 4 rows per block; float4 loads; 4 LSE chains/thread
__global__ void __launch_bounds__(256) f_kernel() {
    __shared__ float gs[NN];
    __shared__ float rm[8], rs[8];
    int t = threadIdx.x;
    for (int j = t; j < NN; j += 256) gs[j] = d_gs[j];
    __syncthreads();
    const float4* gs4 = (const float4*)gs;
    int row0 = blockIdx.x * 4;
    for (int r = 0; r < 4; r++) {
        const float4* Mr = (const float4*)(d_M + (size_t)(row0 + r) * NN);
        float m0 = neg_inf_(), m1 = neg_inf_(), m2 = neg_inf_(), m3 = neg_inf_();
        float s0 = 0.f, s1 = 0.f, s2 = 0.f, s3 = 0.f;
        #pragma unroll
        for (int j = t; j < NN / 4; j += 256) {
            float4 v = Mr[j];
            float4 gv = gs4[j];
            lse_accum(fmaf(v.x, -INV_REG_LN2, gv.x), m0, s0);
            lse_accum(fmaf(v.y, -INV_REG_LN2, gv.y), m1, s1);
            lse_accum(fmaf(v.z, -INV_REG_LN2, gv.z), m2, s2);
            lse_accum(fmaf(v.w, -INV_REG_LN2, gv.w), m3, s3);
        }
        lse_combine(m1, s1, m0, s0);
        lse_combine(m3, s3, m2, s2);
        lse_combine(m2, s2, m0, s0);
        #pragma unroll
        for (int o = 16; o; o >>= 1) {
            float mo = __shfl_down_sync(0xffffffffu, m0, o);
            float so = __shfl_down_sync(0xffffffffu, s0, o);
            lse_combine(mo, so, m0, s0);
        }
        if ((t & 31) == 0) { rm[t >> 5] = m0; rs[t >> 5] = s0; }
        __syncthreads();
        if (t < 32) {
            float m2_ = (t < 8) ? rm[t] : neg_inf_();
            float s2_ = (t < 8) ? rs[t] : 0.f;
            #pragma unroll
            for (int o = 4; o; o >>= 1) {
                float mo = __shfl_down_sync(0xffffffffu, m2_, o);
                float so = __shfl_down_sync(0xffffffffu, s2_, o);
                float mm = fmaxf(m2_, mo);
                s2_ = s2_ * ex2f_(m2_ - mm) + so * ex2f_(mo - mm);
                m2_ = mm;
            }
            if (t == 0) {
                float lse2 = m2_ + lg2f_(s2_);
                float fv = REGC * LOG_A - REG_LN2 * lse2;
                d_f[row0 + r] = fv;
                d_fs[row0 + r] = fv * INV_REG_LN2;
            }
        }
        __syncthreads();
    }
}

// g update: g_j = REG*(log_b - lse_i((f_i - M_ij)/REG))
// grid 128 x 1024; 32-col slab; 4 interleaved LSE chains per thread
__global__ void __launch_bounds__(1024) g_kernel() {
    __shared__ float fs[NN];
    __shared__ float pm[32][33], ps[32][33];
    int t = threadIdx.x;
    for (int j = t; j < NN; j += 1024) fs[j] = d_fs[j];
    __syncthreads();
    int lane = t & 31;
    int rg = t >> 5;                  // 0..31
    int col = blockIdx.x * 32 + lane;
    const float* Mc = d_M + col;
    float m0 = neg_inf_(), m1 = neg_inf_(), m2 = neg_inf_(), m3 = neg_inf_();
    float s0 = 0.f, s1 = 0.f, s2 = 0.f, s3 = 0.f;
    for (int base = 0; base < NN; base += 128) {
        int i0 = base + rg;
        float x0 = fmaf(Mc[(size_t)(i0      ) * NN], -INV_REG_LN2, fs[i0      ]);
        float x1 = fmaf(Mc[(size_t)(i0 + 32 ) * NN], -INV_REG_LN2, fs[i0 + 32 ]);
        float x2 = fmaf(Mc[(size_t)(i0 + 64 ) * NN], -INV_REG_LN2, fs[i0 + 64 ]);
        float x3 = fmaf(Mc[(size_t)(i0 + 96 ) * NN], -INV_REG_LN2, fs[i0 + 96 ]);
        lse_accum(x0, m0, s0);
        lse_accum(x1, m1, s1);
        lse_accum(x2, m2, s2);
        lse_accum(x3, m3, s3);
    }
    lse_combine(m1, s1, m0, s0);
    lse_combine(m3, s3, m2, s2);
    lse_combine(m2, s2, m0, s0);
    pm[rg][lane] = m0; ps[rg][lane] = s0;
    __syncthreads();
    int w = t >> 5;
    float m2_ = pm[lane][w];
    float s2_ = ps[lane][w];
    #pragma unroll
    for (int o = 16; o; o >>= 1) {
        float mo = __shfl_down_sync(0xffffffffu, m2_, o);
        float so = __shfl_down_sync(0xffffffffu, s2_, o);
        float mm = fmaxf(m2_, mo);
        s2_ = s2_ * ex2f_(m2_ - mm) + so * ex2f_(mo - mm);
        m2_ = mm;
    }
    if (lane == 0) {
        float lse2 = m2_ + lg2f_(s2_);
        float gv = REGC * LOG_A - REG_LN2 * lse2;   // log_b == log_a
        int c = blockIdx.x * 32 + w;
        d_g[c] = gv;
        d_gs[c] = gv * INV_REG_LN2;
    }
}

// Final reduction: S1 = sum P*M, S2 = sum P*logP, S3 = sum P
// grid 1024 x 256, 4 rows per block, float4
__global__ void __launch_bounds__(256) final_kernel() {
    __shared__ float gsh[NN];
    __shared__ float r1[8], r2[8], r3[8];
    int t = threadIdx.x;
    for (int j = t; j < NN; j += 256) gsh[j] = d_g[j];
    __syncthreads();
    const float4* g4 = (const float4*)gsh;
    int row0 = blockIdx.x * 4;
    float S1 = 0.f, S2 = 0.f, S3 = 0.f;
    for (int r = 0; r < 4; r++) {
        float fi = d_f[row0 + r];
        const float4* Mr = (const float4*)(d_M + (size_t)(row0 + r) * NN);
        #pragma unroll
        for (int j = t; j < NN / 4; j += 256) {
            float4 Mv = Mr[j];
            float4 gv = g4[j];
            float lp0 = (fi + gv.x - Mv.x);
            float lp1 = (fi + gv.y - Mv.y);
            float lp2 = (fi + gv.z - Mv.z);
            float lp3 = (fi + gv.w - Mv.w);
            float p0 = ex2f_(lp0 * INV_REG_LN2);
            float p1 = ex2f_(lp1 * INV_REG_LN2);
            float p2 = ex2f_(lp2 * INV_REG_LN2);
            float p3 = ex2f_(lp3 * INV_REG_LN2);
            S1 = fmaf(p0, Mv.x, fmaf(p1, Mv.y, fmaf(p2, Mv.z, fmaf(p3, Mv.w, S1))));
            S2 = fmaf(p0, lp0, fmaf(p1, lp1, fmaf(p2, lp2, fmaf(p3, lp3, S2))));
            S3 += (p0 + p1) + (p2 + p3);
        }
    }
    #pragma unroll
    for (int o = 16; o; o >>= 1) {
        S1 += __shfl_down_sync(0xffffffffu, S1, o);
        S2 += __shfl_down_sync(0xffffffffu, S2, o);
        S3 += __shfl_down_sync(0xffffffffu, S3, o);
    }
    if ((t & 31) == 0) { r1[t >> 5] = S1; r2[t >> 5] = S2; r3[t >> 5] = S3; }
    __syncthreads();
    if (t == 0) {
        double a1 = 0, a2 = 0, a3 = 0;
        for (int w = 0; w < 8; w++) { a1 += r1[w]; a2 += r2[w]; a3 += r3[w]; }
        atomicAdd(&d_acc[0], a1);
        atomicAdd(&d_acc[1], a2);
        atomicAdd(&d_acc[2], a3);
    }
}

__global__ void finalize_kernel(float* out) {
    double S1 = d_acc[0], S2 = d_acc[1], S3 = d_acc[2];
    double v = S1 + (double)REGC * (S2 - (double)SUM_LAB * S3 - S3 + 1.0);
    out[0] = (float)v;
}

// ---------------------------------------------------------------------------
extern "C" void kernel_launch(void* const* d_in, const int* in_sizes, int n_in,
                              void* d_out, int out_size) {
    const float* X = (const float*)d_in[0];   // source [4096,512]
    const float* Y = (const float*)d_in[1];   // target [4096,512]

    init_kernel<<<16, 256>>>();
    norms_kernel<<<2 * NN, 128>>>(X, Y);
    dim3 gg(NN / BN, NN / BM);
    gemm_kernel<<<gg, 256>>>(X, Y);
    for (int it = 0; it < 100; it++) {
        f_kernel<<<1024, 256>>>();
        g_kernel<<<128, 1024>>>();
    }
    final_kernel<<<1024, 256>>>();
    finalize_kernel<<<1, 1>>>((float*)d_out);
}

// round 4
// speedup vs baseline: 1.1944x; 1.1227x over previous
#include <cuda_runtime.h>
#include <math.h>

// Problem constants
#define NN 4096
#define DD 512
#define REGC 1.0f
#define INV_REG_LN2 1.4426950408889634f   // 1/(REG*ln2)
#define REG_LN2     0.6931471805599453f   // REG*ln2
#define LOG_A       (-8.317766166719343f) // -log(4096)
#define SUM_LAB     (-16.635532333438686f) // log_a + log_b
#define SAFE_ITERS 6
#define SHIFT_MARGIN 8.0f

// Scratch (device globals; no allocations allowed)
__device__ float d_M[(size_t)NN * NN];   // 64MB cost matrix
__device__ float d_f[NN], d_fs[NN];      // f and f/(REG*ln2)
__device__ float d_g[NN], d_gs[NN];
__device__ float d_x2[NN], d_y2[NN];
__device__ float d_rowmax[NN], d_colmax[NN];   // max of shifted argument (base-2 domain)
__device__ double d_acc[3];              // S1, S2, S3

__device__ __forceinline__ float ex2f_(float x) {
    float y; asm("ex2.approx.ftz.f32 %0, %1;" : "=f"(y) : "f"(x)); return y;
}
__device__ __forceinline__ float lg2f_(float x) {
    float y; asm("lg2.approx.f32 %0, %1;" : "=f"(y) : "f"(x)); return y;
}
__device__ __forceinline__ float neg_inf_() { return __int_as_float(0xff800000); }

// Branchless streaming LSE step (base-2 domain), used in safe iterations
__device__ __forceinline__ void lse_accum(float x, float& m, float& s) {
    float d = x - m;
    float e = ex2f_(0.f - fabsf(d));
    bool gt = d > 0.f;
    s = fmaf(s, gt ? e : 1.f, gt ? 1.f : e);
    m = gt ? x : m;
}
__device__ __forceinline__ void lse_combine(float mo, float so, float& m, float& s) {
    float mm = fmaxf(m, mo);
    s = s * ex2f_(m - mm) + so * ex2f_(mo - mm);
    m = mm;
}

// ---------------------------------------------------------------------------
__global__ void init_kernel() {
    int t = blockIdx.x * blockDim.x + threadIdx.x;
    if (t < 3) d_acc[t] = 0.0;
    if (t < NN) { d_g[t] = 0.f; d_gs[t] = 0.f; d_f[t] = 0.f; d_fs[t] = 0.f; }
}

__global__ void norms_kernel(const float* __restrict__ X, const float* __restrict__ Y) {
    int row = blockIdx.x;
    const float* p = (row < NN) ? (X + (size_t)row * DD) : (Y + (size_t)(row - NN) * DD);
    int t = threadIdx.x;
    float4 v = ((const float4*)p)[t];
    float s = v.x * v.x + v.y * v.y + v.z * v.z + v.w * v.w;
    #pragma unroll
    for (int o = 16; o; o >>= 1) s += __shfl_down_sync(0xffffffffu, s, o);
    __shared__ float sm[4];
    if ((t & 31) == 0) sm[t >> 5] = s;
    __syncthreads();
    if (t == 0) {
        float r = sm[0] + sm[1] + sm[2] + sm[3];
        if (row < NN) d_x2[row] = r; else d_y2[row - NN] = r;
    }
}

// ---------------------------------------------------------------------------
// SGEMM: M[i][j] = max(x2[i] + y2[j] - 2 * dot(X_i, Y_j), 0)
#define BM 128
#define BN 128
#define BK 8
__global__ void __launch_bounds__(256, 2) gemm_kernel(const float* __restrict__ X,
                                                      const float* __restrict__ Y) {
    __shared__ float As[BK][BM];
    __shared__ float Bs[BK][BN];
    int tid = threadIdx.x;
    int tx = tid & 15, ty = tid >> 4;
    int bx = blockIdx.x, by = blockIdx.y;

    int mloc = tid >> 1;
    int kq = (tid & 1) * 4;
    const float* pA = X + (size_t)(by * BM + mloc) * DD + kq;
    const float* pB = Y + (size_t)(bx * BN + mloc) * DD + kq;

    float acc[8][8];
    #pragma unroll
    for (int i = 0; i < 8; i++)
        #pragma unroll
        for (int j = 0; j < 8; j++) acc[i][j] = 0.f;

    float4 a4 = *(const float4*)pA;
    float4 b4 = *(const float4*)pB;

    const int NKT = DD / BK;
    for (int kt = 0; kt < NKT; kt++) {
        As[kq + 0][mloc] = a4.x; As[kq + 1][mloc] = a4.y;
        As[kq + 2][mloc] = a4.z; As[kq + 3][mloc] = a4.w;
        Bs[kq + 0][mloc] = b4.x; Bs[kq + 1][mloc] = b4.y;
        Bs[kq + 2][mloc] = b4.z; Bs[kq + 3][mloc] = b4.w;
        __syncthreads();
        if (kt + 1 < NKT) {
            a4 = *(const float4*)(pA + (kt + 1) * BK);
            b4 = *(const float4*)(pB + (kt + 1) * BK);
        }
        #pragma unroll
        for (int k = 0; k < BK; k++) {
            float a[8], b[8];
            *(float4*)(&a[0]) = *(const float4*)(&As[k][ty * 8]);
            *(float4*)(&a[4]) = *(const float4*)(&As[k][ty * 8 + 4]);
            *(float4*)(&b[0]) = *(const float4*)(&Bs[k][tx * 8]);
            *(float4*)(&b[4]) = *(const float4*)(&Bs[k][tx * 8 + 4]);
            #pragma unroll
            for (int i = 0; i < 8; i++)
                #pragma unroll
                for (int j = 0; j < 8; j++)
                    acc[i][j] = fmaf(a[i], b[j], acc[i][j]);
        }
        __syncthreads();
    }

    int r0 = by * BM + ty * 8;
    int c0 = bx * BN + tx * 8;
    float y2v[8];
    #pragma unroll
    for (int j = 0; j < 8; j++) y2v[j] = d_y2[c0 + j];
    #pragma unroll
    for (int i = 0; i < 8; i++) {
        float x2v = d_x2[r0 + i];
        float out[8];
        #pragma unroll
        for (int j = 0; j < 8; j++)
            out[j] = fmaxf(x2v + y2v[j] - 2.f * acc[i][j], 0.f);
        float* dst = d_M + (size_t)(r0 + i) * NN + c0;
        *(float4*)(dst)     = *(float4*)(&out[0]);
        *(float4*)(dst + 4) = *(float4*)(&out[4]);
    }
}

// ---------------------------------------------------------------------------
// SAFE (online) f update, also records row max. grid 1024 x 256, 4 rows/block.
__global__ void __launch_bounds__(256) f_safe_kernel() {
    __shared__ float gs[NN];
    __shared__ float rm[8], rs[8];
    int t = threadIdx.x;
    for (int j = t; j < NN; j += 256) gs[j] = d_gs[j];
    __syncthreads();
    const float4* gs4 = (const float4*)gs;
    int row0 = blockIdx.x * 4;
    for (int r = 0; r < 4; r++) {
        const float4* Mr = (const float4*)(d_M + (size_t)(row0 + r) * NN);
        float m0 = neg_inf_(), m1 = neg_inf_(), m2 = neg_inf_(), m3 = neg_inf_();
        float s0 = 0.f, s1 = 0.f, s2 = 0.f, s3 = 0.f;
        #pragma unroll
        for (int j = t; j < NN / 4; j += 256) {
            float4 v = Mr[j];
            float4 gv = gs4[j];
            lse_accum(fmaf(v.x, -INV_REG_LN2, gv.x), m0, s0);
            lse_accum(fmaf(v.y, -INV_REG_LN2, gv.y), m1, s1);
            lse_accum(fmaf(v.z, -INV_REG_LN2, gv.z), m2, s2);
            lse_accum(fmaf(v.w, -INV_REG_LN2, gv.w), m3, s3);
        }
        lse_combine(m1, s1, m0, s0);
        lse_combine(m3, s3, m2, s2);
        lse_combine(m2, s2, m0, s0);
        #pragma unroll
        for (int o = 16; o; o >>= 1) {
            float mo = __shfl_down_sync(0xffffffffu, m0, o);
            float so = __shfl_down_sync(0xffffffffu, s0, o);
            lse_combine(mo, so, m0, s0);
        }
        if ((t & 31) == 0) { rm[t >> 5] = m0; rs[t >> 5] = s0; }
        __syncthreads();
        if (t < 32) {
            float m2_ = (t < 8) ? rm[t] : neg_inf_();
            float s2_ = (t < 8) ? rs[t] : 0.f;
            #pragma unroll
            for (int o = 4; o; o >>= 1) {
                float mo = __shfl_down_sync(0xffffffffu, m2_, o);
                float so = __shfl_down_sync(0xffffffffu, s2_, o);
                float mm = fmaxf(m2_, mo);
                s2_ = s2_ * ex2f_(m2_ - mm) + so * ex2f_(mo - mm);
                m2_ = mm;
            }
            if (t == 0) {
                float lse2 = m2_ + lg2f_(s2_);
                float fv = REGC * LOG_A - REG_LN2 * lse2;
                d_f[row0 + r] = fv;
                d_fs[row0 + r] = fv * INV_REG_LN2;
                d_rowmax[row0 + r] = m2_;
            }
        }
        __syncthreads();
    }
}

// SAFE (online) g update, also records col max. grid 128 x 1024.
__global__ void __launch_bounds__(1024) g_safe_kernel() {
    __shared__ float fs[NN];
    __shared__ float pm[32][33], ps[32][33];
    int t = threadIdx.x;
    for (int j = t; j < NN; j += 1024) fs[j] = d_fs[j];
    __syncthreads();
    int lane = t & 31;
    int rg = t >> 5;
    int col = blockIdx.x * 32 + lane;
    const float* Mc = d_M + col;
    float m0 = neg_inf_(), m1 = neg_inf_(), m2 = neg_inf_(), m3 = neg_inf_();
    float s0 = 0.f, s1 = 0.f, s2 = 0.f, s3 = 0.f;
    for (int base = 0; base < NN; base += 128) {
        int i0 = base + rg;
        float x0 = fmaf(Mc[(size_t)(i0      ) * NN], -INV_REG_LN2, fs[i0      ]);
        float x1 = fmaf(Mc[(size_t)(i0 + 32 ) * NN], -INV_REG_LN2, fs[i0 + 32 ]);
        float x2 = fmaf(Mc[(size_t)(i0 + 64 ) * NN], -INV_REG_LN2, fs[i0 + 64 ]);
        float x3 = fmaf(Mc[(size_t)(i0 + 96 ) * NN], -INV_REG_LN2, fs[i0 + 96 ]);
        lse_accum(x0, m0, s0);
        lse_accum(x1, m1, s1);
        lse_accum(x2, m2, s2);
        lse_accum(x3, m3, s3);
    }
    lse_combine(m1, s1, m0, s0);
    lse_combine(m3, s3, m2, s2);
    lse_combine(m2, s2, m0, s0);
    pm[rg][lane] = m0; ps[rg][lane] = s0;
    __syncthreads();
    int w = t >> 5;
    float m2_ = pm[lane][w];
    float s2_ = ps[lane][w];
    #pragma unroll
    for (int o = 16; o; o >>= 1) {
        float mo = __shfl_down_sync(0xffffffffu, m2_, o);
        float so = __shfl_down_sync(0xffffffffu, s2_, o);
        float mm = fmaxf(m2_, mo);
        s2_ = s2_ * ex2f_(m2_ - mm) + so * ex2f_(mo - mm);
        m2_ = mm;
    }
    if (lane == 0) {
        float lse2 = m2_ + lg2f_(s2_);
        float gv = REGC * LOG_A - REG_LN2 * lse2;
        int c = blockIdx.x * 32 + w;
        d_g[c] = gv;
        d_gs[c] = gv * INV_REG_LN2;
        d_colmax[c] = m2_;
    }
}

// ---------------------------------------------------------------------------
// SHIFTED f update: 4 rows in parallel per block (64 threads/row).
// s += ex2(x - C) with C fixed per row (prevmax + margin); track new max via FMAX.
__global__ void __launch_bounds__(256) f_shift_kernel() {
    __shared__ float gs[NN];
    __shared__ float red_s[8], red_m[8];
    int t = threadIdx.x;
    for (int j = t; j < NN; j += 256) gs[j] = d_gs[j];
    __syncthreads();
    int r = t >> 6;          // row within block 0..3
    int l = t & 63;          // lane within row 0..63
    int row = blockIdx.x * 4 + r;
    const float4* Mr = (const float4*)(d_M + (size_t)row * NN);
    const float4* G4 = (const float4*)gs;
    float C = d_rowmax[row] + SHIFT_MARGIN;
    float s0 = 0.f, s1 = 0.f, s2 = 0.f, s3 = 0.f;
    float m0 = neg_inf_(), m1 = neg_inf_(), m2 = neg_inf_(), m3 = neg_inf_();
    #pragma unroll
    for (int k = 0; k < 16; k += 8) {
        float4 v[8], gv[8];
        #pragma unroll
        for (int q = 0; q < 8; q++) v[q] = Mr[l + (k + q) * 64];
        #pragma unroll
        for (int q = 0; q < 8; q++) gv[q] = G4[l + (k + q) * 64];
        #pragma unroll
        for (int q = 0; q < 8; q++) {
            float xa = fmaf(v[q].x, -INV_REG_LN2, gv[q].x);
            float xb = fmaf(v[q].y, -INV_REG_LN2, gv[q].y);
            float xc = fmaf(v[q].z, -INV_REG_LN2, gv[q].z);
            float xd = fmaf(v[q].w, -INV_REG_LN2, gv[q].w);
            s0 += ex2f_(xa - C); m0 = fmaxf(m0, xa);
            s1 += ex2f_(xb - C); m1 = fmaxf(m1, xb);
            s2 += ex2f_(xc - C); m2 = fmaxf(m2, xc);
            s3 += ex2f_(xd - C); m3 = fmaxf(m3, xd);
        }
    }
    float s = (s0 + s1) + (s2 + s3);
    float m = fmaxf(fmaxf(m0, m1), fmaxf(m2, m3));
    #pragma unroll
    for (int o = 16; o; o >>= 1) {
        s += __shfl_down_sync(0xffffffffu, s, o);
        m = fmaxf(m, __shfl_down_sync(0xffffffffu, m, o));
    }
    if ((t & 31) == 0) { red_s[t >> 5] = s; red_m[t >> 5] = m; }
    __syncthreads();
    if (t < 4) {
        float stot = red_s[2 * t] + red_s[2 * t + 1];
        float mtot = fmaxf(red_m[2 * t], red_m[2 * t + 1]);
        int rr = blockIdx.x * 4 + t;
        float Cr = d_rowmax[rr] + SHIFT_MARGIN;
        float lse2 = Cr + lg2f_(stot);
        float fv = REGC * LOG_A - REG_LN2 * lse2;
        d_f[rr] = fv;
        d_fs[rr] = fv * INV_REG_LN2;
        d_rowmax[rr] = mtot;
    }
}

// SHIFTED g update: 32-col slabs, 8 loads in flight, plain add/max reduction.
__global__ void __launch_bounds__(1024) g_shift_kernel() {
    __shared__ float fs[NN];
    __shared__ float pm[32][33], ps[32][33];
    int t = threadIdx.x;
    for (int j = t; j < NN; j += 1024) fs[j] = d_fs[j];
    __syncthreads();
    int lane = t & 31;
    int rg = t >> 5;
    int col = blockIdx.x * 32 + lane;
    const float* Mc = d_M + col;
    float C = d_colmax[col] + SHIFT_MARGIN;
    float s0 = 0.f, s1 = 0.f, s2 = 0.f, s3 = 0.f;
    float m0 = neg_inf_(), m1 = neg_inf_(), m2 = neg_inf_(), m3 = neg_inf_();
    for (int base = 0; base < NN; base += 256) {
        int i0 = base + rg;
        float a0 = Mc[(size_t)(i0       ) * NN];
        float a1 = Mc[(size_t)(i0 + 32  ) * NN];
        float a2 = Mc[(size_t)(i0 + 64  ) * NN];
        float a3 = Mc[(size_t)(i0 + 96  ) * NN];
        float a4 = Mc[(size_t)(i0 + 128 ) * NN];
        float a5 = Mc[(size_t)(i0 + 160 ) * NN];
        float a6 = Mc[(size_t)(i0 + 192 ) * NN];
        float a7 = Mc[(size_t)(i0 + 224 ) * NN];
        float x0 = fmaf(a0, -INV_REG_LN2, fs[i0      ]);
        float x1 = fmaf(a1, -INV_REG_LN2, fs[i0 + 32 ]);
        float x2 = fmaf(a2, -INV_REG_LN2, fs[i0 + 64 ]);
        float x3 = fmaf(a3, -INV_REG_LN2, fs[i0 + 96 ]);
        float x4 = fmaf(a4, -INV_REG_LN2, fs[i0 + 128]);
        float x5 = fmaf(a5, -INV_REG_LN2, fs[i0 + 160]);
        float x6 = fmaf(a6, -INV_REG_LN2, fs[i0 + 192]);
        float x7 = fmaf(a7, -INV_REG_LN2, fs[i0 + 224]);
        s0 += ex2f_(x0 - C); m0 = fmaxf(m0, x0);
        s1 += ex2f_(x1 - C); m1 = fmaxf(m1, x1);
        s2 += ex2f_(x2 - C); m2 = fmaxf(m2, x2);
        s3 += ex2f_(x3 - C); m3 = fmaxf(m3, x3);
        s0 += ex2f_(x4 - C); m0 = fmaxf(m0, x4);
        s1 += ex2f_(x5 - C); m1 = fmaxf(m1, x5);
        s2 += ex2f_(x6 - C); m2 = fmaxf(m2, x6);
        s3 += ex2f_(x7 - C); m3 = fmaxf(m3, x7);
    }
    ps[rg][lane] = (s0 + s1) + (s2 + s3);
    pm[rg][lane] = fmaxf(fmaxf(m0, m1), fmaxf(m2, m3));
    __syncthreads();
    int w = t >> 5;
    float s2_ = ps[lane][w];
    float m2_ = pm[lane][w];
    #pragma unroll
    for (int o = 16; o; o >>= 1) {
        s2_ += __shfl_down_sync(0xffffffffu, s2_, o);
        m2_ = fmaxf(m2_, __shfl_down_sync(0xffffffffu, m2_, o));
    }
    if (lane == 0) {
        int c = blockIdx.x * 32 + w;
        float Cc = d_colmax[c] + SHIFT_MARGIN;
        float lse2 = Cc + lg2f_(s2_);
        float gv = REGC * LOG_A - REG_LN2 * lse2;
        d_g[c] = gv;
        d_gs[c] = gv * INV_REG_LN2;
        d_colmax[c] = m2_;
    }
}

// ---------------------------------------------------------------------------
// Final reduction: S1 = sum P*M, S2 = sum P*logP, S3 = sum P
__global__ void __launch_bounds__(256) final_kernel() {
    __shared__ float gsh[NN];
    __shared__ float r1[8], r2[8], r3[8];
    int t = threadIdx.x;
    for (int j = t; j < NN; j += 256) gsh[j] = d_g[j];
    __syncthreads();
    const float4* g4 = (const float4*)gsh;
    int row0 = blockIdx.x * 4;
    float S1 = 0.f, S2 = 0.f, S3 = 0.f;
    for (int r = 0; r < 4; r++) {
        float fi = d_f[row0 + r];
        const float4* Mr = (const float4*)(d_M + (size_t)(row0 + r) * NN);
        #pragma unroll
        for (int j = t; j < NN / 4; j += 256) {
            float4 Mv = Mr[j];
            float4 gv = g4[j];
            float lp0 = (fi + gv.x - Mv.x);
            float lp1 = (fi + gv.y - Mv.y);
            float lp2 = (fi + gv.z - Mv.z);
            float lp3 = (fi + gv.w - Mv.w);
            float p0 = ex2f_(lp0 * INV_REG_LN2);
            float p1 = ex2f_(lp1 * INV_REG_LN2);
            float p2 = ex2f_(lp2 * INV_REG_LN2);
            float p3 = ex2f_(lp3 * INV_REG_LN2);
            S1 = fmaf(p0, Mv.x, fmaf(p1, Mv.y, fmaf(p2, Mv.z, fmaf(p3, Mv.w, S1))));
            S2 = fmaf(p0, lp0, fmaf(p1, lp1, fmaf(p2, lp2, fmaf(p3, lp3, S2))));
            S3 += (p0 + p1) + (p2 + p3);
        }
    }
    #pragma unroll
    for (int o = 16; o; o >>= 1) {
        S1 += __shfl_down_sync(0xffffffffu, S1, o);
        S2 += __shfl_down_sync(0xffffffffu, S2, o);
        S3 += __shfl_down_sync(0xffffffffu, S3, o);
    }
    if ((t & 31) == 0) { r1[t >> 5] = S1; r2[t >> 5] = S2; r3[t >> 5] = S3; }
    __syncthreads();
    if (t == 0) {
        double a1 = 0, a2 = 0, a3 = 0;
        for (int w = 0; w < 8; w++) { a1 += r1[w]; a2 += r2[w]; a3 += r3[w]; }
        atomicAdd(&d_acc[0], a1);
        atomicAdd(&d_acc[1], a2);
        atomicAdd(&d_acc[2], a3);
    }
}

__global__ void finalize_kernel(float* out) {
    double S1 = d_acc[0], S2 = d_acc[1], S3 = d_acc[2];
    double v = S1 + (double)REGC * (S2 - (double)SUM_LAB * S3 - S3 + 1.0);
    out[0] = (float)v;
}

// ---------------------------------------------------------------------------
extern "C" void kernel_launch(void* const* d_in, const int* in_sizes, int n_in,
                              void* d_out, int out_size) {
    const float* X = (const float*)d_in[0];   // source [4096,512]
    const float* Y = (const float*)d_in[1];   // target [4096,512]

    init_kernel<<<16, 256>>>();
    norms_kernel<<<2 * NN, 128>>>(X, Y);
    dim3 gg(NN / BN, NN / BM);
    gemm_kernel<<<gg, 256>>>(X, Y);
    for (int it = 0; it < SAFE_ITERS; it++) {
        f_safe_kernel<<<1024, 256>>>();
        g_safe_kernel<<<128, 1024>>>();
    }
    for (int it = SAFE_ITERS; it < 100; it++) {
        f_shift_kernel<<<1024, 256>>>();
        g_shift_kernel<<<128, 1024>>>();
    }
    final_kernel<<<1024, 256>>>();
    finalize_kernel<<<1, 1>>>((float*)d_out);
}

// round 5
// speedup vs baseline: 1.4201x; 1.1890x over previous
#include <cuda_runtime.h>
#include <math.h>

// Problem constants
#define NN 4096
#define DD 512
#define REGC 1.0f
#define INV_REG_LN2 1.4426950408889634f   // 1/(REG*ln2)
#define REG_LN2     0.6931471805599453f   // REG*ln2
#define LOG_A       (-8.317766166719343f) // -log(4096)
#define SUM_LAB     (-16.635532333438686f) // log_a + log_b
#define SAFE_ITERS 6
#define SHIFT_MARGIN 8.0f
#define QS      32.0f
#define INV_QS  0.03125f
#define KQ      0.045084220027780106f     // INV_REG_LN2 / 32

// Scratch (device globals; no allocations allowed)
__device__ unsigned short d_Mq[(size_t)NN * NN];  // 32MB quantized cost matrix
__device__ float d_f[NN], d_fs[NN];
__device__ float d_g[NN], d_gs[NN];
__device__ float d_x2[NN], d_y2[NN];
__device__ float d_rowmax[NN], d_colmax[NN];
__device__ double d_acc[3];

__device__ __forceinline__ float ex2f_(float x) {
    float y; asm("ex2.approx.ftz.f32 %0, %1;" : "=f"(y) : "f"(x)); return y;
}
__device__ __forceinline__ float lg2f_(float x) {
    float y; asm("lg2.approx.f32 %0, %1;" : "=f"(y) : "f"(x)); return y;
}
__device__ __forceinline__ float neg_inf_() { return __int_as_float(0xff800000); }

__device__ __forceinline__ void lse_accum(float x, float& m, float& s) {
    float d = x - m;
    float e = ex2f_(0.f - fabsf(d));
    bool gt = d > 0.f;
    s = fmaf(s, gt ? e : 1.f, gt ? 1.f : e);
    m = gt ? x : m;
}
__device__ __forceinline__ void lse_combine(float mo, float so, float& m, float& s) {
    float mm = fmaxf(m, mo);
    s = s * ex2f_(m - mm) + so * ex2f_(mo - mm);
    m = mm;
}

// ---------------------------------------------------------------------------
__global__ void init_kernel() {
    int t = blockIdx.x * blockDim.x + threadIdx.x;
    if (t < 3) d_acc[t] = 0.0;
    if (t < NN) { d_g[t] = 0.f; d_gs[t] = 0.f; d_f[t] = 0.f; d_fs[t] = 0.f; }
}

__global__ void norms_kernel(const float* __restrict__ X, const float* __restrict__ Y) {
    int row = blockIdx.x;
    const float* p = (row < NN) ? (X + (size_t)row * DD) : (Y + (size_t)(row - NN) * DD);
    int t = threadIdx.x;
    float4 v = ((const float4*)p)[t];
    float s = v.x * v.x + v.y * v.y + v.z * v.z + v.w * v.w;
    #pragma unroll
    for (int o = 16; o; o >>= 1) s += __shfl_down_sync(0xffffffffu, s, o);
    __shared__ float sm[4];
    if ((t & 31) == 0) sm[t >> 5] = s;
    __syncthreads();
    if (t == 0) {
        float r = sm[0] + sm[1] + sm[2] + sm[3];
        if (row < NN) d_x2[row] = r; else d_y2[row - NN] = r;
    }
}

// ---------------------------------------------------------------------------
// SGEMM: Mq[i][j] = round(32 * max(x2[i] + y2[j] - 2*dot(X_i,Y_j), 0))
#define BM 128
#define BN 128
#define BK 8
__global__ void __launch_bounds__(256, 2) gemm_kernel(const float* __restrict__ X,
                                                      const float* __restrict__ Y) {
    __shared__ float As[BK][BM];
    __shared__ float Bs[BK][BN];
    int tid = threadIdx.x;
    int tx = tid & 15, ty = tid >> 4;
    int bx = blockIdx.x, by = blockIdx.y;

    int mloc = tid >> 1;
    int kq = (tid & 1) * 4;
    const float* pA = X + (size_t)(by * BM + mloc) * DD + kq;
    const float* pB = Y + (size_t)(bx * BN + mloc) * DD + kq;

    float acc[8][8];
    #pragma unroll
    for (int i = 0; i < 8; i++)
        #pragma unroll
        for (int j = 0; j < 8; j++) acc[i][j] = 0.f;

    float4 a4 = *(const float4*)pA;
    float4 b4 = *(const float4*)pB;

    const int NKT = DD / BK;
    for (int kt = 0; kt < NKT; kt++) {
        As[kq + 0][mloc] = a4.x; As[kq + 1][mloc] = a4.y;
        As[kq + 2][mloc] = a4.z; As[kq + 3][mloc] = a4.w;
        Bs[kq + 0][mloc] = b4.x; Bs[kq + 1][mloc] = b4.y;
        Bs[kq + 2][mloc] = b4.z; Bs[kq + 3][mloc] = b4.w;
        __syncthreads();
        if (kt + 1 < NKT) {
            a4 = *(const float4*)(pA + (kt + 1) * BK);
            b4 = *(const float4*)(pB + (kt + 1) * BK);
        }
        #pragma unroll
        for (int k = 0; k < BK; k++) {
            float a[8], b[8];
            *(float4*)(&a[0]) = *(const float4*)(&As[k][ty * 8]);
            *(float4*)(&a[4]) = *(const float4*)(&As[k][ty * 8 + 4]);
            *(float4*)(&b[0]) = *(const float4*)(&Bs[k][tx * 8]);
            *(float4*)(&b[4]) = *(const float4*)(&Bs[k][tx * 8 + 4]);
            #pragma unroll
            for (int i = 0; i < 8; i++)
                #pragma unroll
                for (int j = 0; j < 8; j++)
                    acc[i][j] = fmaf(a[i], b[j], acc[i][j]);
        }
        __syncthreads();
    }

    int r0 = by * BM + ty * 8;
    int c0 = bx * BN + tx * 8;
    float y2v[8];
    #pragma unroll
    for (int j = 0; j < 8; j++) y2v[j] = d_y2[c0 + j];
    #pragma unroll
    for (int i = 0; i < 8; i++) {
        float x2v = d_x2[r0 + i];
        unsigned short q[8];
        #pragma unroll
        for (int j = 0; j < 8; j++) {
            float mv = fmaxf(x2v + y2v[j] - 2.f * acc[i][j], 0.f);
            q[j] = (unsigned short)__float2uint_rn(fminf(mv * QS, 65535.f));
        }
        unsigned short* dst = d_Mq + (size_t)(r0 + i) * NN + c0;
        *(uint4*)dst = *(uint4*)q;
    }
}

// ---------------------------------------------------------------------------
// SAFE (online) f update, records row max. grid 1024 x 256, 4 rows/block.
__global__ void __launch_bounds__(256) f_safe_kernel() {
    __shared__ float gs[NN];
    __shared__ float rm[8], rs[8];
    int t = threadIdx.x;
    for (int j = t; j < NN; j += 256) gs[j] = d_gs[j];
    __syncthreads();
    const float4* gs4 = (const float4*)gs;
    int row0 = blockIdx.x * 4;
    for (int r = 0; r < 4; r++) {
        const uint2* Mr = (const uint2*)(d_Mq + (size_t)(row0 + r) * NN);
        float m0 = neg_inf_(), m1 = neg_inf_(), m2 = neg_inf_(), m3 = neg_inf_();
        float s0 = 0.f, s1 = 0.f, s2 = 0.f, s3 = 0.f;
        #pragma unroll
        for (int j = t; j < NN / 4; j += 256) {
            uint2 v = Mr[j];
            float4 gv = gs4[j];
            float q0 = (float)(v.x & 0xffffu);
            float q1 = (float)(v.x >> 16);
            float q2 = (float)(v.y & 0xffffu);
            float q3 = (float)(v.y >> 16);
            lse_accum(fmaf(q0, -KQ, gv.x), m0, s0);
            lse_accum(fmaf(q1, -KQ, gv.y), m1, s1);
            lse_accum(fmaf(q2, -KQ, gv.z), m2, s2);
            lse_accum(fmaf(q3, -KQ, gv.w), m3, s3);
        }
        lse_combine(m1, s1, m0, s0);
        lse_combine(m3, s3, m2, s2);
        lse_combine(m2, s2, m0, s0);
        #pragma unroll
        for (int o = 16; o; o >>= 1) {
            float mo = __shfl_down_sync(0xffffffffu, m0, o);
            float so = __shfl_down_sync(0xffffffffu, s0, o);
            lse_combine(mo, so, m0, s0);
        }
        if ((t & 31) == 0) { rm[t >> 5] = m0; rs[t >> 5] = s0; }
        __syncthreads();
        if (t < 32) {
            float m2_ = (t < 8) ? rm[t] : neg_inf_();
            float s2_ = (t < 8) ? rs[t] : 0.f;
            #pragma unroll
            for (int o = 4; o; o >>= 1) {
                float mo = __shfl_down_sync(0xffffffffu, m2_, o);
                float so = __shfl_down_sync(0xffffffffu, s2_, o);
                float mm = fmaxf(m2_, mo);
                s2_ = s2_ * ex2f_(m2_ - mm) + so * ex2f_(mo - mm);
                m2_ = mm;
            }
            if (t == 0) {
                float lse2 = m2_ + lg2f_(s2_);
                float fv = REGC * LOG_A - REG_LN2 * lse2;
                d_f[row0 + r] = fv;
                d_fs[row0 + r] = fv * INV_REG_LN2;
                d_rowmax[row0 + r] = m2_;
            }
        }
        __syncthreads();
    }
}

// SAFE (online) g update, records col max. grid 128 x 1024.
__global__ void __launch_bounds__(1024) g_safe_kernel() {
    __shared__ float fs[NN];
    __shared__ float pm[32][33], ps[32][33];
    int t = threadIdx.x;
    for (int j = t; j < NN; j += 1024) fs[j] = d_fs[j];
    __syncthreads();
    int lane = t & 31;
    int rg = t >> 5;
    int col = blockIdx.x * 32 + lane;
    const unsigned short* Mc = d_Mq + col;
    float m0 = neg_inf_(), m1 = neg_inf_(), m2 = neg_inf_(), m3 = neg_inf_();
    float s0 = 0.f, s1 = 0.f, s2 = 0.f, s3 = 0.f;
    for (int base = 0; base < NN; base += 128) {
        int i0 = base + rg;
        float x0 = fmaf((float)Mc[(size_t)(i0      ) * NN], -KQ, fs[i0      ]);
        float x1 = fmaf((float)Mc[(size_t)(i0 + 32 ) * NN], -KQ, fs[i0 + 32 ]);
        float x2 = fmaf((float)Mc[(size_t)(i0 + 64 ) * NN], -KQ, fs[i0 + 64 ]);
        float x3 = fmaf((float)Mc[(size_t)(i0 + 96 ) * NN], -KQ, fs[i0 + 96 ]);
        lse_accum(x0, m0, s0);
        lse_accum(x1, m1, s1);
        lse_accum(x2, m2, s2);
        lse_accum(x3, m3, s3);
    }
    lse_combine(m1, s1, m0, s0);
    lse_combine(m3, s3, m2, s2);
    lse_combine(m2, s2, m0, s0);
    pm[rg][lane] = m0; ps[rg][lane] = s0;
    __syncthreads();
    int w = t >> 5;
    float m2_ = pm[lane][w];
    float s2_ = ps[lane][w];
    #pragma unroll
    for (int o = 16; o; o >>= 1) {
        float mo = __shfl_down_sync(0xffffffffu, m2_, o);
        float so = __shfl_down_sync(0xffffffffu, s2_, o);
        float mm = fmaxf(m2_, mo);
        s2_ = s2_ * ex2f_(m2_ - mm) + so * ex2f_(mo - mm);
        m2_ = mm;
    }
    if (lane == 0) {
        float lse2 = m2_ + lg2f_(s2_);
        float gv = REGC * LOG_A - REG_LN2 * lse2;
        int c = blockIdx.x * 32 + w;
        d_g[c] = gv;
        d_gs[c] = gv * INV_REG_LN2;
        d_colmax[c] = m2_;
    }
}

// ---------------------------------------------------------------------------
// SHIFTED f update: 512 blocks x 512 threads, 8 rows in parallel (64 thr/row).
__global__ void __launch_bounds__(512) f_shift_kernel() {
    __shared__ float gs[NN];
    __shared__ float red_s[16], red_m[16];
    int t = threadIdx.x;
    for (int j = t; j < NN; j += 512) gs[j] = d_gs[j];
    __syncthreads();
    int r = t >> 6;          // row within block 0..7
    int l = t & 63;          // lane within row 0..63
    int row = blockIdx.x * 8 + r;
    const uint4* Mr = (const uint4*)(d_Mq + (size_t)row * NN);   // 512 uint4/row
    const float4* G4 = (const float4*)gs;
    float C = d_rowmax[row] + SHIFT_MARGIN;
    float s0 = 0.f, s1 = 0.f, s2 = 0.f, s3 = 0.f;
    float m0 = neg_inf_(), m1 = neg_inf_(), m2 = neg_inf_(), m3 = neg_inf_();
    #pragma unroll
    for (int k = 0; k < 8; k++) {
        int idx = l + k * 64;
        uint4 v = Mr[idx];
        float4 ga = G4[2 * idx];
        float4 gb = G4[2 * idx + 1];
        float xa = fmaf((float)(v.x & 0xffffu), -KQ, ga.x);
        float xb = fmaf((float)(v.x >> 16),    -KQ, ga.y);
        float xc = fmaf((float)(v.y & 0xffffu), -KQ, ga.z);
        float xd = fmaf((float)(v.y >> 16),    -KQ, ga.w);
        float xe = fmaf((float)(v.z & 0xffffu), -KQ, gb.x);
        float xf = fmaf((float)(v.z >> 16),    -KQ, gb.y);
        float xg = fmaf((float)(v.w & 0xffffu), -KQ, gb.z);
        float xh = fmaf((float)(v.w >> 16),    -KQ, gb.w);
        s0 += ex2f_(xa - C); m0 = fmaxf(m0, xa);
        s1 += ex2f_(xb - C); m1 = fmaxf(m1, xb);
        s2 += ex2f_(xc - C); m2 = fmaxf(m2, xc);
        s3 += ex2f_(xd - C); m3 = fmaxf(m3, xd);
        s0 += ex2f_(xe - C); m0 = fmaxf(m0, xe);
        s1 += ex2f_(xf - C); m1 = fmaxf(m1, xf);
        s2 += ex2f_(xg - C); m2 = fmaxf(m2, xg);
        s3 += ex2f_(xh - C); m3 = fmaxf(m3, xh);
    }
    float s = (s0 + s1) + (s2 + s3);
    float m = fmaxf(fmaxf(m0, m1), fmaxf(m2, m3));
    #pragma unroll
    for (int o = 16; o; o >>= 1) {
        s += __shfl_down_sync(0xffffffffu, s, o);
        m = fmaxf(m, __shfl_down_sync(0xffffffffu, m, o));
    }
    if ((t & 31) == 0) { red_s[t >> 5] = s; red_m[t >> 5] = m; }
    __syncthreads();
    if (t < 8) {
        float stot = red_s[2 * t] + red_s[2 * t + 1];
        float mtot = fmaxf(red_m[2 * t], red_m[2 * t + 1]);
        int rr = blockIdx.x * 8 + t;
        float Cr = d_rowmax[rr] + SHIFT_MARGIN;
        float lse2 = Cr + lg2f_(stot);
        float fv = REGC * LOG_A - REG_LN2 * lse2;
        d_f[rr] = fv;
        d_fs[rr] = fv * INV_REG_LN2;
        d_rowmax[rr] = mtot;
    }
}

// SHIFTED g update: 128 blocks x 1024; 32-col slabs, 8 loads in flight.
__global__ void __launch_bounds__(1024) g_shift_kernel() {
    __shared__ float fs[NN];
    __shared__ float pm[32][33], ps[32][33];
    int t = threadIdx.x;
    for (int j = t; j < NN; j += 1024) fs[j] = d_fs[j];
    __syncthreads();
    int lane = t & 31;
    int rg = t >> 5;
    int col = blockIdx.x * 32 + lane;
    const unsigned short* Mc = d_Mq + col;
    float C = d_colmax[col] + SHIFT_MARGIN;
    float s0 = 0.f, s1 = 0.f, s2 = 0.f, s3 = 0.f;
    float m0 = neg_inf_(), m1 = neg_inf_(), m2 = neg_inf_(), m3 = neg_inf_();
    for (int base = 0; base < NN; base += 256) {
        int i0 = base + rg;
        unsigned short a0 = Mc[(size_t)(i0       ) * NN];
        unsigned short a1 = Mc[(size_t)(i0 + 32  ) * NN];
        unsigned short a2 = Mc[(size_t)(i0 + 64  ) * NN];
        unsigned short a3 = Mc[(size_t)(i0 + 96  ) * NN];
        unsigned short a4 = Mc[(size_t)(i0 + 128 ) * NN];
        unsigned short a5 = Mc[(size_t)(i0 + 160 ) * NN];
        unsigned short a6 = Mc[(size_t)(i0 + 192 ) * NN];
        unsigned short a7 = Mc[(size_t)(i0 + 224 ) * NN];
        float x0 = fmaf((float)a0, -KQ, fs[i0      ]);
        float x1 = fmaf((float)a1, -KQ, fs[i0 + 32 ]);
        float x2 = fmaf((float)a2, -KQ, fs[i0 + 64 ]);
        float x3 = fmaf((float)a3, -KQ, fs[i0 + 96 ]);
        float x4 = fmaf((float)a4, -KQ, fs[i0 + 128]);
        float x5 = fmaf((float)a5, -KQ, fs[i0 + 160]);
        float x6 = fmaf((float)a6, -KQ, fs[i0 + 192]);
        float x7 = fmaf((float)a7, -KQ, fs[i0 + 224]);
        s0 += ex2f_(x0 - C); m0 = fmaxf(m0, x0);
        s1 += ex2f_(x1 - C); m1 = fmaxf(m1, x1);
        s2 += ex2f_(x2 - C); m2 = fmaxf(m2, x2);
        s3 += ex2f_(x3 - C); m3 = fmaxf(m3, x3);
        s0 += ex2f_(x4 - C); m0 = fmaxf(m0, x4);
        s1 += ex2f_(x5 - C); m1 = fmaxf(m1, x5);
        s2 += ex2f_(x6 - C); m2 = fmaxf(m2, x6);
        s3 += ex2f_(x7 - C); m3 = fmaxf(m3, x7);
    }
    ps[rg][lane] = (s0 + s1) + (s2 + s3);
    pm[rg][lane] = fmaxf(fmaxf(m0, m1), fmaxf(m2, m3));
    __syncthreads();
    int w = t >> 5;
    float s2_ = ps[lane][w];
    float m2_ = pm[lane][w];
    #pragma unroll
    for (int o = 16; o; o >>= 1) {
        s2_ += __shfl_down_sync(0xffffffffu, s2_, o);
        m2_ = fmaxf(m2_, __shfl_down_sync(0xffffffffu, m2_, o));
    }
    if (lane == 0) {
        int c = blockIdx.x * 32 + w;
        float Cc = d_colmax[c] + SHIFT_MARGIN;
        float lse2 = Cc + lg2f_(s2_);
        float gv = REGC * LOG_A - REG_LN2 * lse2;
        d_g[c] = gv;
        d_gs[c] = gv * INV_REG_LN2;
        d_colmax[c] = m2_;
    }
}

// ---------------------------------------------------------------------------
// Final reduction: S1 = sum P*M, S2 = sum P*logP, S3 = sum P
__global__ void __launch_bounds__(256) final_kernel() {
    __shared__ float gsh[NN];
    __shared__ float r1[8], r2[8], r3[8];
    int t = threadIdx.x;
    for (int j = t; j < NN; j += 256) gsh[j] = d_g[j];
    __syncthreads();
    const float4* g4 = (const float4*)gsh;
    int row0 = blockIdx.x * 4;
    float S1 = 0.f, S2 = 0.f, S3 = 0.f;
    for (int r = 0; r < 4; r++) {
        float fi = d_f[row0 + r];
        const uint2* Mr = (const uint2*)(d_Mq + (size_t)(row0 + r) * NN);
        #pragma unroll
        for (int j = t; j < NN / 4; j += 256) {
            uint2 v = Mr[j];
            float4 gv = g4[j];
            float M0 = (float)(v.x & 0xffffu) * INV_QS;
            float M1 = (float)(v.x >> 16)    * INV_QS;
            float M2 = (float)(v.y & 0xffffu) * INV_QS;
            float M3 = (float)(v.y >> 16)    * INV_QS;
            float lp0 = (fi + gv.x - M0);
            float lp1 = (fi + gv.y - M1);
            float lp2 = (fi + gv.z - M2);
            float lp3 = (fi + gv.w - M3);
            float p0 = ex2f_(lp0 * INV_REG_LN2);
            float p1 = ex2f_(lp1 * INV_REG_LN2);
            float p2 = ex2f_(lp2 * INV_REG_LN2);
            float p3 = ex2f_(lp3 * INV_REG_LN2);
            S1 = fmaf(p0, M0, fmaf(p1, M1, fmaf(p2, M2, fmaf(p3, M3, S1))));
            S2 = fmaf(p0, lp0, fmaf(p1, lp1, fmaf(p2, lp2, fmaf(p3, lp3, S2))));
            S3 += (p0 + p1) + (p2 + p3);
        }
    }
    #pragma unroll
    for (int o = 16; o; o >>= 1) {
        S1 += __shfl_down_sync(0xffffffffu, S1, o);
        S2 += __shfl_down_sync(0xffffffffu, S2, o);
        S3 += __shfl_down_sync(0xffffffffu, S3, o);
    }
    if ((t & 31) == 0) { r1[t >> 5] = S1; r2[t >> 5] = S2; r3[t >> 5] = S3; }
    __syncthreads();
    if (t == 0) {
        double a1 = 0, a2 = 0, a3 = 0;
        for (int w = 0; w < 8; w++) { a1 += r1[w]; a2 += r2[w]; a3 += r3[w]; }
        atomicAdd(&d_acc[0], a1);
        atomicAdd(&d_acc[1], a2);
        atomicAdd(&d_acc[2], a3);
    }
}

__global__ void finalize_kernel(float* out) {
    double S1 = d_acc[0], S2 = d_acc[1], S3 = d_acc[2];
    double v = S1 + (double)REGC * (S2 - (double)SUM_LAB * S3 - S3 + 1.0);
    out[0] = (float)v;
}

// ---------------------------------------------------------------------------
extern "C" void kernel_launch(void* const* d_in, const int* in_sizes, int n_in,
                              void* d_out, int out_size) {
    const float* X = (const float*)d_in[0];   // source [4096,512]
    const float* Y = (const float*)d_in[1];   // target [4096,512]

    init_kernel<<<16, 256>>>();
    norms_kernel<<<2 * NN, 128>>>(X, Y);
    dim3 gg(NN / BN, NN / BM);
    gemm_kernel<<<gg, 256>>>(X, Y);
    for (int it = 0; it < SAFE_ITERS; it++) {
        f_safe_kernel<<<1024, 256>>>();
        g_safe_kernel<<<128, 1024>>>();
    }
    for (int it = SAFE_ITERS; it < 100; it++) {
        f_shift_kernel<<<512, 512>>>();
        g_shift_kernel<<<128, 1024>>>();
    }
    final_kernel<<<1024, 256>>>();
    finalize_kernel<<<1, 1>>>((float*)d_out);
}

// round 7
// speedup vs baseline: 1.6146x; 1.1370x over previous
#include <cuda_runtime.h>
#include <math.h>

// Problem constants
#define NN 4096
#define DD 512
#define REGC 1.0f
#define INV_REG_LN2 1.4426950408889634f   // 1/(REG*ln2)
#define REG_LN2     0.6931471805599453f   // REG*ln2
#define LOG_A       (-8.317766166719343f) // -log(4096)
#define SUM_LAB     (-16.635532333438686f) // log_a + log_b
#define SAFE_ITERS 3
#define DENSE_SHIFT_ITERS 9               // dense pairs total = 12
#define SHIFT_MARGIN 8.0f
#define QS      32.0f
#define INV_QS  0.03125f
#define KQ      0.045084220027780106f     // INV_REG_LN2 / 32
#define TH      34.0f                     // active-set threshold (base-2 units)
#define SCAP    32                        // entries cap per row/col

// Scratch (device globals; no allocations allowed)
__device__ unsigned short d_Mq[(size_t)NN * NN];  // 32MB quantized cost matrix
__device__ float d_f[NN], d_fs[NN];
__device__ float d_g[NN], d_gs[NN];
__device__ float d_x2[NN], d_y2[NN];
__device__ float d_rowmax[NN], d_colmax[NN];
__device__ unsigned int d_rowcnt[NN], d_colcnt[NN];
__device__ unsigned int d_rowlist[(size_t)NN * SCAP];
__device__ unsigned int d_collist[(size_t)NN * SCAP];
__device__ double d_acc[3];

__device__ __forceinline__ float ex2f_(float x) {
    float y; asm("ex2.approx.ftz.f32 %0, %1;" : "=f"(y) : "f"(x)); return y;
}
__device__ __forceinline__ float lg2f_(float x) {
    float y; asm("lg2.approx.f32 %0, %1;" : "=f"(y) : "f"(x)); return y;
}
__device__ __forceinline__ float neg_inf_() { return __int_as_float(0xff800000); }

__device__ __forceinline__ void lse_accum(float x, float& m, float& s) {
    float d = x - m;
    float e = ex2f_(0.f - fabsf(d));
    bool gt = d > 0.f;
    s = fmaf(s, gt ? e : 1.f, gt ? 1.f : e);
    m = gt ? x : m;
}
__device__ __forceinline__ void lse_combine(float mo, float so, float& m, float& s) {
    float mm = fmaxf(m, mo);
    s = s * ex2f_(m - mm) + so * ex2f_(mo - mm);
    m = mm;
}

// ---------------------------------------------------------------------------
__global__ void init_kernel() {
    int t = blockIdx.x * blockDim.x + threadIdx.x;
    if (t < 3) d_acc[t] = 0.0;
    if (t < NN) { d_g[t] = 0.f; d_gs[t] = 0.f; d_f[t] = 0.f; d_fs[t] = 0.f; }
}

__global__ void zero_cnt_kernel() {
    int t = blockIdx.x * blockDim.x + threadIdx.x;
    if (t < NN) { d_rowcnt[t] = 0u; d_colcnt[t] = 0u; }
}

__global__ void norms_kernel(const float* __restrict__ X, const float* __restrict__ Y) {
    int row = blockIdx.x;
    const float* p = (row < NN) ? (X + (size_t)row * DD) : (Y + (size_t)(row - NN) * DD);
    int t = threadIdx.x;
    float4 v = ((const float4*)p)[t];
    float s = v.x * v.x + v.y * v.y + v.z * v.z + v.w * v.w;
    #pragma unroll
    for (int o = 16; o; o >>= 1) s += __shfl_down_sync(0xffffffffu, s, o);
    __shared__ float sm[4];
    if ((t & 31) == 0) sm[t >> 5] = s;
    __syncthreads();
    if (t == 0) {
        float r = sm[0] + sm[1] + sm[2] + sm[3];
        if (row < NN) d_x2[row] = r; else d_y2[row - NN] = r;
    }
}

// ---------------------------------------------------------------------------
// SGEMM: Mq[i][j] = round(32 * max(x2[i] + y2[j] - 2*dot(X_i,Y_j), 0))
#define BM 128
#define BN 128
#define BK 8
__global__ void __launch_bounds__(256, 2) gemm_kernel(const float* __restrict__ X,
                                                      const float* __restrict__ Y) {
    __shared__ float As[BK][BM];
    __shared__ float Bs[BK][BN];
    int tid = threadIdx.x;
    int tx = tid & 15, ty = tid >> 4;
    int bx = blockIdx.x, by = blockIdx.y;

    int mloc = tid >> 1;
    int kq = (tid & 1) * 4;
    const float* pA = X + (size_t)(by * BM + mloc) * DD + kq;
    const float* pB = Y + (size_t)(bx * BN + mloc) * DD + kq;

    float acc[8][8];
    #pragma unroll
    for (int i = 0; i < 8; i++)
        #pragma unroll
        for (int j = 0; j < 8; j++) acc[i][j] = 0.f;

    float4 a4 = *(const float4*)pA;
    float4 b4 = *(const float4*)pB;

    const int NKT = DD / BK;
    for (int kt = 0; kt < NKT; kt++) {
        As[kq + 0][mloc] = a4.x; As[kq + 1][mloc] = a4.y;
        As[kq + 2][mloc] = a4.z; As[kq + 3][mloc] = a4.w;
        Bs[kq + 0][mloc] = b4.x; Bs[kq + 1][mloc] = b4.y;
        Bs[kq + 2][mloc] = b4.z; Bs[kq + 3][mloc] = b4.w;
        __syncthreads();
        if (kt + 1 < NKT) {
            a4 = *(const float4*)(pA + (kt + 1) * BK);
            b4 = *(const float4*)(pB + (kt + 1) * BK);
        }
        #pragma unroll
        for (int k = 0; k < BK; k++) {
            float a[8], b[8];
            *(float4*)(&a[0]) = *(const float4*)(&As[k][ty * 8]);
            *(float4*)(&a[4]) = *(const float4*)(&As[k][ty * 8 + 4]);
            *(float4*)(&b[0]) = *(const float4*)(&Bs[k][tx * 8]);
            *(float4*)(&b[4]) = *(const float4*)(&Bs[k][tx * 8 + 4]);
            #pragma unroll
            for (int i = 0; i < 8; i++)
                #pragma unroll
                for (int j = 0; j < 8; j++)
                    acc[i][j] = fmaf(a[i], b[j], acc[i][j]);
        }
        __syncthreads();
    }

    int r0 = by * BM + ty * 8;
    int c0 = bx * BN + tx * 8;
    float y2v[8];
    #pragma unroll
    for (int j = 0; j < 8; j++) y2v[j] = d_y2[c0 + j];
    #pragma unroll
    for (int i = 0; i < 8; i++) {
        float x2v = d_x2[r0 + i];
        unsigned short q[8];
        #pragma unroll
        for (int j = 0; j < 8; j++) {
            float mv = fmaxf(x2v + y2v[j] - 2.f * acc[i][j], 0.f);
            q[j] = (unsigned short)__float2uint_rn(fminf(mv * QS, 65535.f));
        }
        unsigned short* dst = d_Mq + (size_t)(r0 + i) * NN + c0;
        *(uint4*)dst = *(uint4*)q;
    }
}

// ---------------------------------------------------------------------------
// SAFE (online) f update, records row max. grid 1024 x 256, 4 rows/block.
__global__ void __launch_bounds__(256) f_safe_kernel() {
    __shared__ float gs[NN];
    __shared__ float rm[8], rs[8];
    int t = threadIdx.x;
    for (int j = t; j < NN; j += 256) gs[j] = d_gs[j];
    __syncthreads();
    const float4* gs4 = (const float4*)gs;
    int row0 = blockIdx.x * 4;
    for (int r = 0; r < 4; r++) {
        const uint2* Mr = (const uint2*)(d_Mq + (size_t)(row0 + r) * NN);
        float m0 = neg_inf_(), m1 = neg_inf_(), m2 = neg_inf_(), m3 = neg_inf_();
        float s0 = 0.f, s1 = 0.f, s2 = 0.f, s3 = 0.f;
        #pragma unroll
        for (int j = t; j < NN / 4; j += 256) {
            uint2 v = Mr[j];
            float4 gv = gs4[j];
            lse_accum(fmaf((float)(v.x & 0xffffu), -KQ, gv.x), m0, s0);
            lse_accum(fmaf((float)(v.x >> 16),    -KQ, gv.y), m1, s1);
            lse_accum(fmaf((float)(v.y & 0xffffu), -KQ, gv.z), m2, s2);
            lse_accum(fmaf((float)(v.y >> 16),    -KQ, gv.w), m3, s3);
        }
        lse_combine(m1, s1, m0, s0);
        lse_combine(m3, s3, m2, s2);
        lse_combine(m2, s2, m0, s0);
        #pragma unroll
        for (int o = 16; o; o >>= 1) {
            float mo = __shfl_down_sync(0xffffffffu, m0, o);
            float so = __shfl_down_sync(0xffffffffu, s0, o);
            lse_combine(mo, so, m0, s0);
        }
        if ((t & 31) == 0) { rm[t >> 5] = m0; rs[t >> 5] = s0; }
        __syncthreads();
        if (t < 32) {
            float m2_ = (t < 8) ? rm[t] : neg_inf_();
            float s2_ = (t < 8) ? rs[t] : 0.f;
            #pragma unroll
            for (int o = 4; o; o >>= 1) {
                float mo = __shfl_down_sync(0xffffffffu, m2_, o);
                float so = __shfl_down_sync(0xffffffffu, s2_, o);
                float mm = fmaxf(m2_, mo);
                s2_ = s2_ * ex2f_(m2_ - mm) + so * ex2f_(mo - mm);
                m2_ = mm;
            }
            if (t == 0) {
                float lse2 = m2_ + lg2f_(s2_);
                float fv = REGC * LOG_A - REG_LN2 * lse2;
                d_f[row0 + r] = fv;
                d_fs[row0 + r] = fv * INV_REG_LN2;
                d_rowmax[row0 + r] = m2_;
            }
        }
        __syncthreads();
    }
}

// SAFE (online) g update, records col max. grid 128 x 1024.
__global__ void __launch_bounds__(1024) g_safe_kernel() {
    __shared__ float fs[NN];
    __shared__ float pm[32][33], ps[32][33];
    int t = threadIdx.x;
    for (int j = t; j < NN; j += 1024) fs[j] = d_fs[j];
    __syncthreads();
    int lane = t & 31;
    int rg = t >> 5;
    int col = blockIdx.x * 32 + lane;
    const unsigned short* Mc = d_Mq + col;
    float m0 = neg_inf_(), m1 = neg_inf_(), m2 = neg_inf_(), m3 = neg_inf_();
    float s0 = 0.f, s1 = 0.f, s2 = 0.f, s3 = 0.f;
    for (int base = 0; base < NN; base += 128) {
        int i0 = base + rg;
        float x0 = fmaf((float)Mc[(size_t)(i0      ) * NN], -KQ, fs[i0      ]);
        float x1 = fmaf((float)Mc[(size_t)(i0 + 32 ) * NN], -KQ, fs[i0 + 32 ]);
        float x2 = fmaf((float)Mc[(size_t)(i0 + 64 ) * NN], -KQ, fs[i0 + 64 ]);
        float x3 = fmaf((float)Mc[(size_t)(i0 + 96 ) * NN], -KQ, fs[i0 + 96 ]);
        lse_accum(x0, m0, s0);
        lse_accum(x1, m1, s1);
        lse_accum(x2, m2, s2);
        lse_accum(x3, m3, s3);
    }
    lse_combine(m1, s1, m0, s0);
    lse_combine(m3, s3, m2, s2);
    lse_combine(m2, s2, m0, s0);
    pm[rg][lane] = m0; ps[rg][lane] = s0;
    __syncthreads();
    int w = t >> 5;
    float m2_ = pm[lane][w];
    float s2_ = ps[lane][w];
    #pragma unroll
    for (int o = 16; o; o >>= 1) {
        float mo = __shfl_down_sync(0xffffffffu, m2_, o);
        float so = __shfl_down_sync(0xffffffffu, s2_, o);
        float mm = fmaxf(m2_, mo);
        s2_ = s2_ * ex2f_(m2_ - mm) + so * ex2f_(mo - mm);
        m2_ = mm;
    }
    if (lane == 0) {
        float lse2 = m2_ + lg2f_(s2_);
        float gv = REGC * LOG_A - REG_LN2 * lse2;
        int c = blockIdx.x * 32 + w;
        d_g[c] = gv;
        d_gs[c] = gv * INV_REG_LN2;
        d_colmax[c] = m2_;
    }
}

// ---------------------------------------------------------------------------
// SHIFTED dense f update: 512 blocks x 512 threads, 8 rows/block.
__global__ void __launch_bounds__(512) f_shift_kernel() {
    __shared__ float gs[NN];
    __shared__ float red_s[16], red_m[16];
    int t = threadIdx.x;
    for (int j = t; j < NN; j += 512) gs[j] = d_gs[j];
    __syncthreads();
    int r = t >> 6;
    int l = t & 63;
    int row = blockIdx.x * 8 + r;
    const uint4* Mr = (const uint4*)(d_Mq + (size_t)row * NN);
    const float4* G4 = (const float4*)gs;
    float C = d_rowmax[row] + SHIFT_MARGIN;
    float s0 = 0.f, s1 = 0.f, s2 = 0.f, s3 = 0.f;
    float m0 = neg_inf_(), m1 = neg_inf_(), m2 = neg_inf_(), m3 = neg_inf_();
    #pragma unroll
    for (int k = 0; k < 8; k++) {
        int idx = l + k * 64;
        uint4 v = Mr[idx];
        float4 ga = G4[2 * idx];
        float4 gb = G4[2 * idx + 1];
        float xa = fmaf((float)(v.x & 0xffffu), -KQ, ga.x);
        float xb = fmaf((float)(v.x >> 16),    -KQ, ga.y);
        float xc = fmaf((float)(v.y & 0xffffu), -KQ, ga.z);
        float xd = fmaf((float)(v.y >> 16),    -KQ, ga.w);
        float xe = fmaf((float)(v.z & 0xffffu), -KQ, gb.x);
        float xf = fmaf((float)(v.z >> 16),    -KQ, gb.y);
        float xg = fmaf((float)(v.w & 0xffffu), -KQ, gb.z);
        float xh = fmaf((float)(v.w >> 16),    -KQ, gb.w);
        s0 += ex2f_(xa - C); m0 = fmaxf(m0, xa);
        s1 += ex2f_(xb - C); m1 = fmaxf(m1, xb);
        s2 += ex2f_(xc - C); m2 = fmaxf(m2, xc);
        s3 += ex2f_(xd - C); m3 = fmaxf(m3, xd);
        s0 += ex2f_(xe - C); m0 = fmaxf(m0, xe);
        s1 += ex2f_(xf - C); m1 = fmaxf(m1, xf);
        s2 += ex2f_(xg - C); m2 = fmaxf(m2, xg);
        s3 += ex2f_(xh - C); m3 = fmaxf(m3, xh);
    }
    float s = (s0 + s1) + (s2 + s3);
    float m = fmaxf(fmaxf(m0, m1), fmaxf(m2, m3));
    #pragma unroll
    for (int o = 16; o; o >>= 1) {
        s += __shfl_down_sync(0xffffffffu, s, o);
        m = fmaxf(m, __shfl_down_sync(0xffffffffu, m, o));
    }
    if ((t & 31) == 0) { red_s[t >> 5] = s; red_m[t >> 5] = m; }
    __syncthreads();
    if (t < 8) {
        float stot = red_s[2 * t] + red_s[2 * t + 1];
        float mtot = fmaxf(red_m[2 * t], red_m[2 * t + 1]);
        int rr = blockIdx.x * 8 + t;
        float Cr = d_rowmax[rr] + SHIFT_MARGIN;
        float lse2 = Cr + lg2f_(stot);
        float fv = REGC * LOG_A - REG_LN2 * lse2;
        d_f[rr] = fv;
        d_fs[rr] = fv * INV_REG_LN2;
        d_rowmax[rr] = mtot;
    }
}

// SHIFTED dense g update.
__global__ void __launch_bounds__(1024) g_shift_kernel() {
    __shared__ float fs[NN];
    __shared__ float pm[32][33], ps[32][33];
    int t = threadIdx.x;
    for (int j = t; j < NN; j += 1024) fs[j] = d_fs[j];
    __syncthreads();
    int lane = t & 31;
    int rg = t >> 5;
    int col = blockIdx.x * 32 + lane;
    const unsigned short* Mc = d_Mq + col;
    float C = d_colmax[col] + SHIFT_MARGIN;
    float s0 = 0.f, s1 = 0.f, s2 = 0.f, s3 = 0.f;
    float m0 = neg_inf_(), m1 = neg_inf_(), m2 = neg_inf_(), m3 = neg_inf_();
    for (int base = 0; base < NN; base += 256) {
        int i0 = base + rg;
        unsigned short a0 = Mc[(size_t)(i0       ) * NN];
        unsigned short a1 = Mc[(size_t)(i0 + 32  ) * NN];
        unsigned short a2 = Mc[(size_t)(i0 + 64  ) * NN];
        unsigned short a3 = Mc[(size_t)(i0 + 96  ) * NN];
        unsigned short a4 = Mc[(size_t)(i0 + 128 ) * NN];
        unsigned short a5 = Mc[(size_t)(i0 + 160 ) * NN];
        unsigned short a6 = Mc[(size_t)(i0 + 192 ) * NN];
        unsigned short a7 = Mc[(size_t)(i0 + 224 ) * NN];
        float x0 = fmaf((float)a0, -KQ, fs[i0      ]);
        float x1 = fmaf((float)a1, -KQ, fs[i0 + 32 ]);
        float x2 = fmaf((float)a2, -KQ, fs[i0 + 64 ]);
        float x3 = fmaf((float)a3, -KQ, fs[i0 + 96 ]);
        float x4 = fmaf((float)a4, -KQ, fs[i0 + 128]);
        float x5 = fmaf((float)a5, -KQ, fs[i0 + 160]);
        float x6 = fmaf((float)a6, -KQ, fs[i0 + 192]);
        float x7 = fmaf((float)a7, -KQ, fs[i0 + 224]);
        s0 += ex2f_(x0 - C); m0 = fmaxf(m0, x0);
        s1 += ex2f_(x1 - C); m1 = fmaxf(m1, x1);
        s2 += ex2f_(x2 - C); m2 = fmaxf(m2, x2);
        s3 += ex2f_(x3 - C); m3 = fmaxf(m3, x3);
        s0 += ex2f_(x4 - C); m0 = fmaxf(m0, x4);
        s1 += ex2f_(x5 - C); m1 = fmaxf(m1, x5);
        s2 += ex2f_(x6 - C); m2 = fmaxf(m2, x6);
        s3 += ex2f_(x7 - C); m3 = fmaxf(m3, x7);
    }
    ps[rg][lane] = (s0 + s1) + (s2 + s3);
    pm[rg][lane] = fmaxf(fmaxf(m0, m1), fmaxf(m2, m3));
    __syncthreads();
    int w = t >> 5;
    float s2_ = ps[lane][w];
    float m2_ = pm[lane][w];
    #pragma unroll
    for (int o = 16; o; o >>= 1) {
        s2_ += __shfl_down_sync(0xffffffffu, s2_, o);
        m2_ = fmaxf(m2_, __shfl_down_sync(0xffffffffu, m2_, o));
    }
    if (lane == 0) {
        int c = blockIdx.x * 32 + w;
        float Cc = d_colmax[c] + SHIFT_MARGIN;
        float lse2 = Cc + lg2f_(s2_);
        float gv = REGC * LOG_A - REG_LN2 * lse2;
        d_g[c] = gv;
        d_gs[c] = gv * INV_REG_LN2;
        d_colmax[c] = m2_;
    }
}

// ---------------------------------------------------------------------------
// BUILD: scan Mq once; collect active entries per row and per column.
// Row test:  gs_j - q*KQ >= rowmax_i - TH
// Col test:  fs_i - q*KQ >= colmax_j - TH
__global__ void __launch_bounds__(256) build_kernel() {
    __shared__ float gsm[NN];
    __shared__ float cth[NN];
    int t = threadIdx.x;
    for (int k = t; k < NN; k += 256) {
        gsm[k] = d_gs[k];
        cth[k] = d_colmax[k] - TH;
    }
    __syncthreads();
    int row0 = blockIdx.x * 16;
    for (int r = 0; r < 16; r++) {
        int row = row0 + r;
        float rth = d_rowmax[row] - TH;
        float fsv = d_fs[row];
        const uint4* Mr = (const uint4*)(d_Mq + (size_t)row * NN);
        for (int idx = t; idx < NN / 8; idx += 256) {
            uint4 v = Mr[idx];
            int j0 = idx * 8;
            unsigned int qs[8];
            qs[0] = v.x & 0xffffu; qs[1] = v.x >> 16;
            qs[2] = v.y & 0xffffu; qs[3] = v.y >> 16;
            qs[4] = v.z & 0xffffu; qs[5] = v.z >> 16;
            qs[6] = v.w & 0xffffu; qs[7] = v.w >> 16;
            #pragma unroll
            for (int h = 0; h < 8; h++) {
                int j = j0 + h;
                float qf = (float)qs[h];
                float xr = fmaf(qf, -KQ, gsm[j]);
                if (xr >= rth) {
                    unsigned int p = atomicAdd(&d_rowcnt[row], 1u);
                    if (p < SCAP) d_rowlist[(size_t)row * SCAP + p] = ((unsigned int)j << 16) | qs[h];
                }
                float xc = fmaf(qf, -KQ, fsv);
                if (xc >= cth[j]) {
                    unsigned int p = atomicAdd(&d_colcnt[j], 1u);
                    if (p < SCAP) d_collist[(size_t)j * SCAP + p] = ((unsigned int)row << 16) | qs[h];
                }
            }
        }
    }
}

// ---------------------------------------------------------------------------
// SPARSE Sinkhorn: one cluster of 8 CTAs x 512 threads; thread-per-row/col.
// Runs npairs (f,g) iterations fully in-kernel with cluster barriers.
__global__ void __launch_bounds__(512) __cluster_dims__(8, 1, 1)
sparse_kernel(int npairs) {
    __shared__ float vsh[NN];
    int t = threadIdx.x;
    int id = blockIdx.x * 512 + t;       // row id (f pass) / col id (g pass)

    for (int it = 0; it < npairs; it++) {
        // ---------- f pass (needs gs) ----------
        for (int k = t; k < NN; k += 512) vsh[k] = d_gs[k];
        __syncthreads();
        {
            int n = (int)d_rowcnt[id]; if (n > SCAP) n = SCAP;
            unsigned int e[SCAP];
            float x[SCAP];
            #pragma unroll
            for (int k = 0; k < SCAP; k++)
                if (k < n) e[k] = d_rowlist[(size_t)id * SCAP + k];
            #pragma unroll
            for (int k = 0; k < SCAP; k++)
                if (k < n) x[k] = fmaf((float)(e[k] & 0xffffu), -KQ, vsh[e[k] >> 16]);
            float m = neg_inf_();
            #pragma unroll
            for (int k = 0; k < SCAP; k++)
                if (k < n) m = fmaxf(m, x[k]);
            float s = 0.f;
            #pragma unroll
            for (int k = 0; k < SCAP; k++)
                if (k < n) s += ex2f_(x[k] - m);
            float lse2 = m + lg2f_(s);
            float fv = REGC * LOG_A - REG_LN2 * lse2;
            d_f[id] = fv;
            d_fs[id] = fv * INV_REG_LN2;
            d_rowmax[id] = m;
        }
        __threadfence();
        asm volatile("barrier.cluster.arrive.aligned;" ::: "memory");
        asm volatile("barrier.cluster.wait.aligned;" ::: "memory");

        // ---------- g pass (needs fs) ----------
        for (int k = t; k < NN; k += 512) vsh[k] = d_fs[k];
        __syncthreads();
        {
            int n = (int)d_colcnt[id]; if (n > SCAP) n = SCAP;
            unsigned int e[SCAP];
            float x[SCAP];
            #pragma unroll
            for (int k = 0; k < SCAP; k++)
                if (k < n) e[k] = d_collist[(size_t)id * SCAP + k];
            #pragma unroll
            for (int k = 0; k < SCAP; k++)
                if (k < n) x[k] = fmaf((float)(e[k] & 0xffffu), -KQ, vsh[e[k] >> 16]);
            float m = neg_inf_();
            #pragma unroll
            for (int k = 0; k < SCAP; k++)
                if (k < n) m = fmaxf(m, x[k]);
            float s = 0.f;
            #pragma unroll
            for (int k = 0; k < SCAP; k++)
                if (k < n) s += ex2f_(x[k] - m);
            float lse2 = m + lg2f_(s);
            float gv = REGC * LOG_A - REG_LN2 * lse2;   // log_b == log_a
            d_g[id] = gv;
            d_gs[id] = gv * INV_REG_LN2;
            d_colmax[id] = m;
        }
        __threadfence();
        asm volatile("barrier.cluster.arrive.aligned;" ::: "memory");
        asm volatile("barrier.cluster.wait.aligned;" ::: "memory");
    }
}

// ---------------------------------------------------------------------------
// Final reduction: S1 = sum P*M, S2 = sum P*logP, S3 = sum P (dense, exact)
__global__ void __launch_bounds__(256) final_kernel() {
    __shared__ float gsh[NN];
    __shared__ float r1[8], r2[8], r3[8];
    int t = threadIdx.x;
    for (int j = t; j < NN; j += 256) gsh[j] = d_g[j];
    __syncthreads();
    const float4* g4 = (const float4*)gsh;
    int row0 = blockIdx.x * 4;
    float S1 = 0.f, S2 = 0.f, S3 = 0.f;
    for (int r = 0; r < 4; r++) {
        float fi = d_f[row0 + r];
        const uint2* Mr = (const uint2*)(d_Mq + (size_t)(row0 + r) * NN);
        #pragma unroll
        for (int j = t; j < NN / 4; j += 256) {
            uint2 v = Mr[j];
            float4 gv = g4[j];
            float M0 = (float)(v.x & 0xffffu) * INV_QS;
            float M1 = (float)(v.x >> 16)    * INV_QS;
            float M2 = (float)(v.y & 0xffffu) * INV_QS;
            float M3 = (float)(v.y >> 16)    * INV_QS;
            float lp0 = (fi + gv.x - M0);
            float lp1 = (fi + gv.y - M1);
            float lp2 = (fi + gv.z - M2);
            float lp3 = (fi + gv.w - M3);
            float p0 = ex2f_(lp0 * INV_REG_LN2);
            float p1 = ex2f_(lp1 * INV_REG_LN2);
            float p2 = ex2f_(lp2 * INV_REG_LN2);
            float p3 = ex2f_(lp3 * INV_REG_LN2);
            S1 = fmaf(p0, M0, fmaf(p1, M1, fmaf(p2, M2, fmaf(p3, M3, S1))));
            S2 = fmaf(p0, lp0, fmaf(p1, lp1, fmaf(p2, lp2, fmaf(p3, lp3, S2))));
            S3 += (p0 + p1) + (p2 + p3);
        }
    }
    #pragma unroll
    for (int o = 16; o; o >>= 1) {
        S1 += __shfl_down_sync(0xffffffffu, S1, o);
        S2 += __shfl_down_sync(0xffffffffu, S2, o);
        S3 += __shfl_down_sync(0xffffffffu, S3, o);
    }
    if ((t & 31) == 0) { r1[t >> 5] = S1; r2[t >> 5] = S2; r3[t >> 5] = S3; }
    __syncthreads();
    if (t == 0) {
        double a1 = 0, a2 = 0, a3 = 0;
        for (int w = 0; w < 8; w++) { a1 += r1[w]; a2 += r2[w]; a3 += r3[w]; }
        atomicAdd(&d_acc[0], a1);
        atomicAdd(&d_acc[1], a2);
        atomicAdd(&d_acc[2], a3);
    }
}

__global__ void finalize_kernel(float* out) {
    double S1 = d_acc[0], S2 = d_acc[1], S3 = d_acc[2];
    double v = S1 + (double)REGC * (S2 - (double)SUM_LAB * S3 - S3 + 1.0);
    out[0] = (float)v;
}

// ---------------------------------------------------------------------------
extern "C" void kernel_launch(void* const* d_in, const int* in_sizes, int n_in,
                              void* d_out, int out_size) {
    const float* X = (const float*)d_in[0];   // source [4096,512]
    const float* Y = (const float*)d_in[1];   // target [4096,512]

    init_kernel<<<16, 256>>>();
    norms_kernel<<<2 * NN, 128>>>(X, Y);
    dim3 gg(NN / BN, NN / BM);
    gemm_kernel<<<gg, 256>>>(X, Y);

    // 12 dense pairs: 3 safe + 9 shifted
    for (int it = 0; it < SAFE_ITERS; it++) {
        f_safe_kernel<<<1024, 256>>>();
        g_safe_kernel<<<128, 1024>>>();
    }
    for (int it = 0; it < DENSE_SHIFT_ITERS; it++) {
        f_shift_kernel<<<512, 512>>>();
        g_shift_kernel<<<128, 1024>>>();
    }

    // Sparse phase: 88 pairs in 3 segments with list rebuilds
    zero_cnt_kernel<<<16, 256>>>();
    build_kernel<<<256, 256>>>();
    sparse_kernel<<<8, 512>>>(30);

    zero_cnt_kernel<<<16, 256>>>();
    build_kernel<<<256, 256>>>();
    sparse_kernel<<<8, 512>>>(30);

    zero_cnt_kernel<<<16, 256>>>();
    build_kernel<<<256, 256>>>();
    sparse_kernel<<<8, 512>>>(28);

    final_kernel<<<1024, 256>>>();
    finalize_kernel<<<1, 1>>>((float*)d_out);
}

// round 8
// speedup vs baseline: 1.8795x; 1.1640x over previous
#include <cuda_runtime.h>
#include <math.h>

// Problem constants
#define NN 4096
#define DD 512
#define REGC 1.0f
#define INV_REG_LN2 1.4426950408889634f   // 1/(REG*ln2)
#define REG_LN2     0.6931471805599453f   // REG*ln2
#define LOG_A       (-8.317766166719343f) // -log(4096)
#define SUM_LAB     (-16.635532333438686f) // log_a + log_b
#define SAFE_ITERS 3
#define DENSE_SHIFT_ITERS 9               // dense pairs total = 12
#define SHIFT_MARGIN 8.0f
#define QS      32.0f
#define INV_QS  0.03125f
#define KQ      0.045084220027780106f     // INV_REG_LN2 / 32
#define TH      34.0f                     // active-set threshold (base-2 units)
#define SCAP    96                        // entries cap per row/col

// Scratch (device globals; no allocations allowed)
__device__ unsigned short d_Mq[(size_t)NN * NN];  // 32MB quantized cost matrix
__device__ float d_f[NN], d_fs[NN];
__device__ float d_g[NN], d_gs[NN];
__device__ float d_x2[NN], d_y2[NN];
__device__ float d_rowmax[NN], d_colmax[NN];
__device__ unsigned int d_rowcnt[NN], d_colcnt[NN];
__device__ unsigned int d_rowlist[(size_t)NN * SCAP];
__device__ unsigned int d_collist[(size_t)NN * SCAP];
__device__ double d_acc[3];

__device__ __forceinline__ float ex2f_(float x) {
    float y; asm("ex2.approx.ftz.f32 %0, %1;" : "=f"(y) : "f"(x)); return y;
}
__device__ __forceinline__ float lg2f_(float x) {
    float y; asm("lg2.approx.f32 %0, %1;" : "=f"(y) : "f"(x)); return y;
}
__device__ __forceinline__ float neg_inf_() { return __int_as_float(0xff800000); }

#define FMA2(d, a, b, c) \
    asm("fma.rn.f32x2 %0, %1, %2, %3;" : "=l"(d) : "l"(a), "l"(b), "l"(c))
#define DUP_F32X2(r, f) \
    asm("mov.b64 %0, {%1, %1};" : "=l"(r) : "r"(f))
#define UNPACK2(lo, hi, v) \
    asm("mov.b64 {%0, %1}, %2;" : "=r"(lo), "=r"(hi) : "l"(v))

__device__ __forceinline__ void lse_accum(float x, float& m, float& s) {
    float d = x - m;
    float e = ex2f_(0.f - fabsf(d));
    bool gt = d > 0.f;
    s = fmaf(s, gt ? e : 1.f, gt ? 1.f : e);
    m = gt ? x : m;
}
__device__ __forceinline__ void lse_combine(float mo, float so, float& m, float& s) {
    float mm = fmaxf(m, mo);
    s = s * ex2f_(m - mm) + so * ex2f_(mo - mm);
    m = mm;
}

// ---------------------------------------------------------------------------
__global__ void init_kernel() {
    int t = blockIdx.x * blockDim.x + threadIdx.x;
    if (t < 3) d_acc[t] = 0.0;
    if (t < NN) { d_g[t] = 0.f; d_gs[t] = 0.f; d_f[t] = 0.f; d_fs[t] = 0.f; }
}

__global__ void zero_cnt_kernel() {
    int t = blockIdx.x * blockDim.x + threadIdx.x;
    if (t < NN) { d_rowcnt[t] = 0u; d_colcnt[t] = 0u; }
}

__global__ void norms_kernel(const float* __restrict__ X, const float* __restrict__ Y) {
    int row = blockIdx.x;
    const float* p = (row < NN) ? (X + (size_t)row * DD) : (Y + (size_t)(row - NN) * DD);
    int t = threadIdx.x;
    float4 v = ((const float4*)p)[t];
    float s = v.x * v.x + v.y * v.y + v.z * v.z + v.w * v.w;
    #pragma unroll
    for (int o = 16; o; o >>= 1) s += __shfl_down_sync(0xffffffffu, s, o);
    __shared__ float sm[4];
    if ((t & 31) == 0) sm[t >> 5] = s;
    __syncthreads();
    if (t == 0) {
        float r = sm[0] + sm[1] + sm[2] + sm[3];
        if (row < NN) d_x2[row] = r; else d_y2[row - NN] = r;
    }
}

// ---------------------------------------------------------------------------
// SGEMM with packed f32x2 FMA: Mq[i][j] = round(32*max(x2[i]+y2[j]-2*dot,0))
#define BM 128
#define BN 128
#define BK 8
__global__ void __launch_bounds__(256, 2) gemm_kernel(const float* __restrict__ X,
                                                      const float* __restrict__ Y) {
    __shared__ float As[BK][BM];
    __shared__ float Bs[BK][BN];
    int tid = threadIdx.x;
    int tx = tid & 15, ty = tid >> 4;
    int bx = blockIdx.x, by = blockIdx.y;

    int mloc = tid >> 1;
    int kq = (tid & 1) * 4;
    const float* pA = X + (size_t)(by * BM + mloc) * DD + kq;
    const float* pB = Y + (size_t)(bx * BN + mloc) * DD + kq;

    // accp[p][j] packs rows (2p, 2p+1) for column j
    unsigned long long accp[4][8];
    #pragma unroll
    for (int p = 0; p < 4; p++)
        #pragma unroll
        for (int j = 0; j < 8; j++) accp[p][j] = 0ull;

    float4 a4 = *(const float4*)pA;
    float4 b4 = *(const float4*)pB;

    const int NKT = DD / BK;
    for (int kt = 0; kt < NKT; kt++) {
        As[kq + 0][mloc] = a4.x; As[kq + 1][mloc] = a4.y;
        As[kq + 2][mloc] = a4.z; As[kq + 3][mloc] = a4.w;
        Bs[kq + 0][mloc] = b4.x; Bs[kq + 1][mloc] = b4.y;
        Bs[kq + 2][mloc] = b4.z; Bs[kq + 3][mloc] = b4.w;
        __syncthreads();
        if (kt + 1 < NKT) {
            a4 = *(const float4*)(pA + (kt + 1) * BK);
            b4 = *(const float4*)(pB + (kt + 1) * BK);
        }
        #pragma unroll
        for (int k = 0; k < BK; k++) {
            unsigned long long ap[4];
            #pragma unroll
            for (int p = 0; p < 4; p++)
                ap[p] = *(const unsigned long long*)(&As[k][ty * 8 + 2 * p]);
            float bl[8];
            *(float4*)(&bl[0]) = *(const float4*)(&Bs[k][tx * 8]);
            *(float4*)(&bl[4]) = *(const float4*)(&Bs[k][tx * 8 + 4]);
            unsigned long long bd[8];
            #pragma unroll
            for (int j = 0; j < 8; j++) DUP_F32X2(bd[j], __float_as_uint(bl[j]));
            #pragma unroll
            for (int p = 0; p < 4; p++)
                #pragma unroll
                for (int j = 0; j < 8; j++)
                    FMA2(accp[p][j], ap[p], bd[j], accp[p][j]);
        }
        __syncthreads();
    }

    int r0 = by * BM + ty * 8;
    int c0 = bx * BN + tx * 8;
    float y2v[8];
    #pragma unroll
    for (int j = 0; j < 8; j++) y2v[j] = d_y2[c0 + j];
    #pragma unroll
    for (int p = 0; p < 4; p++) {
        float x2lo = d_x2[r0 + 2 * p];
        float x2hi = d_x2[r0 + 2 * p + 1];
        unsigned short qlo[8], qhi[8];
        #pragma unroll
        for (int j = 0; j < 8; j++) {
            unsigned int ulo, uhi;
            UNPACK2(ulo, uhi, accp[p][j]);
            float mlo = fmaxf(x2lo + y2v[j] - 2.f * __uint_as_float(ulo), 0.f);
            float mhi = fmaxf(x2hi + y2v[j] - 2.f * __uint_as_float(uhi), 0.f);
            qlo[j] = (unsigned short)__float2uint_rn(fminf(mlo * QS, 65535.f));
            qhi[j] = (unsigned short)__float2uint_rn(fminf(mhi * QS, 65535.f));
        }
        unsigned short* dst = d_Mq + (size_t)(r0 + 2 * p) * NN + c0;
        *(uint4*)dst = *(uint4*)qlo;
        *(uint4*)(dst + NN) = *(uint4*)qhi;
    }
}

// ---------------------------------------------------------------------------
// SAFE (online) f update, records row max. grid 1024 x 256, 4 rows/block.
__global__ void __launch_bounds__(256) f_safe_kernel() {
    __shared__ float gs[NN];
    __shared__ float rm[8], rs[8];
    int t = threadIdx.x;
    for (int j = t; j < NN; j += 256) gs[j] = d_gs[j];
    __syncthreads();
    const float4* gs4 = (const float4*)gs;
    int row0 = blockIdx.x * 4;
    for (int r = 0; r < 4; r++) {
        const uint2* Mr = (const uint2*)(d_Mq + (size_t)(row0 + r) * NN);
        float m0 = neg_inf_(), m1 = neg_inf_(), m2 = neg_inf_(), m3 = neg_inf_();
        float s0 = 0.f, s1 = 0.f, s2 = 0.f, s3 = 0.f;
        #pragma unroll
        for (int j = t; j < NN / 4; j += 256) {
            uint2 v = Mr[j];
            float4 gv = gs4[j];
            lse_accum(fmaf((float)(v.x & 0xffffu), -KQ, gv.x), m0, s0);
            lse_accum(fmaf((float)(v.x >> 16),    -KQ, gv.y), m1, s1);
            lse_accum(fmaf((float)(v.y & 0xffffu), -KQ, gv.z), m2, s2);
            lse_accum(fmaf((float)(v.y >> 16),    -KQ, gv.w), m3, s3);
        }
        lse_combine(m1, s1, m0, s0);
        lse_combine(m3, s3, m2, s2);
        lse_combine(m2, s2, m0, s0);
        #pragma unroll
        for (int o = 16; o; o >>= 1) {
            float mo = __shfl_down_sync(0xffffffffu, m0, o);
            float so = __shfl_down_sync(0xffffffffu, s0, o);
            lse_combine(mo, so, m0, s0);
        }
        if ((t & 31) == 0) { rm[t >> 5] = m0; rs[t >> 5] = s0; }
        __syncthreads();
        if (t < 32) {
            float m2_ = (t < 8) ? rm[t] : neg_inf_();
            float s2_ = (t < 8) ? rs[t] : 0.f;
            #pragma unroll
            for (int o = 4; o; o >>= 1) {
                float mo = __shfl_down_sync(0xffffffffu, m2_, o);
                float so = __shfl_down_sync(0xffffffffu, s2_, o);
                float mm = fmaxf(m2_, mo);
                s2_ = s2_ * ex2f_(m2_ - mm) + so * ex2f_(mo - mm);
                m2_ = mm;
            }
            if (t == 0) {
                float lse2 = m2_ + lg2f_(s2_);
                float fv = REGC * LOG_A - REG_LN2 * lse2;
                d_f[row0 + r] = fv;
                d_fs[row0 + r] = fv * INV_REG_LN2;
                d_rowmax[row0 + r] = m2_;
            }
        }
        __syncthreads();
    }
}

// SAFE (online) g update, records col max. grid 128 x 1024.
__global__ void __launch_bounds__(1024) g_safe_kernel() {
    __shared__ float fs[NN];
    __shared__ float pm[32][33], ps[32][33];
    int t = threadIdx.x;
    for (int j = t; j < NN; j += 1024) fs[j] = d_fs[j];
    __syncthreads();
    int lane = t & 31;
    int rg = t >> 5;
    int col = blockIdx.x * 32 + lane;
    const unsigned short* Mc = d_Mq + col;
    float m0 = neg_inf_(), m1 = neg_inf_(), m2 = neg_inf_(), m3 = neg_inf_();
    float s0 = 0.f, s1 = 0.f, s2 = 0.f, s3 = 0.f;
    for (int base = 0; base < NN; base += 128) {
        int i0 = base + rg;
        float x0 = fmaf((float)Mc[(size_t)(i0      ) * NN], -KQ, fs[i0      ]);
        float x1 = fmaf((float)Mc[(size_t)(i0 + 32 ) * NN], -KQ, fs[i0 + 32 ]);
        float x2 = fmaf((float)Mc[(size_t)(i0 + 64 ) * NN], -KQ, fs[i0 + 64 ]);
        float x3 = fmaf((float)Mc[(size_t)(i0 + 96 ) * NN], -KQ, fs[i0 + 96 ]);
        lse_accum(x0, m0, s0);
        lse_accum(x1, m1, s1);
        lse_accum(x2, m2, s2);
        lse_accum(x3, m3, s3);
    }
    lse_combine(m1, s1, m0, s0);
    lse_combine(m3, s3, m2, s2);
    lse_combine(m2, s2, m0, s0);
    pm[rg][lane] = m0; ps[rg][lane] = s0;
    __syncthreads();
    int w = t >> 5;
    float m2_ = pm[lane][w];
    float s2_ = ps[lane][w];
    #pragma unroll
    for (int o = 16; o; o >>= 1) {
        float mo = __shfl_down_sync(0xffffffffu, m2_, o);
        float so = __shfl_down_sync(0xffffffffu, s2_, o);
        float mm = fmaxf(m2_, mo);
        s2_ = s2_ * ex2f_(m2_ - mm) + so * ex2f_(mo - mm);
        m2_ = mm;
    }
    if (lane == 0) {
        float lse2 = m2_ + lg2f_(s2_);
        float gv = REGC * LOG_A - REG_LN2 * lse2;
        int c = blockIdx.x * 32 + w;
        d_g[c] = gv;
        d_gs[c] = gv * INV_REG_LN2;
        d_colmax[c] = m2_;
    }
}

// ---------------------------------------------------------------------------
// SHIFTED dense f update: 512 blocks x 512 threads, 8 rows/block.
__global__ void __launch_bounds__(512) f_shift_kernel() {
    __shared__ float gs[NN];
    __shared__ float red_s[16], red_m[16];
    int t = threadIdx.x;
    for (int j = t; j < NN; j += 512) gs[j] = d_gs[j];
    __syncthreads();
    int r = t >> 6;
    int l = t & 63;
    int row = blockIdx.x * 8 + r;
    const uint4* Mr = (const uint4*)(d_Mq + (size_t)row * NN);
    const float4* G4 = (const float4*)gs;
    float C = d_rowmax[row] + SHIFT_MARGIN;
    float s0 = 0.f, s1 = 0.f, s2 = 0.f, s3 = 0.f;
    float m0 = neg_inf_(), m1 = neg_inf_(), m2 = neg_inf_(), m3 = neg_inf_();
    #pragma unroll
    for (int k = 0; k < 8; k++) {
        int idx = l + k * 64;
        uint4 v = Mr[idx];
        float4 ga = G4[2 * idx];
        float4 gb = G4[2 * idx + 1];
        float xa = fmaf((float)(v.x & 0xffffu), -KQ, ga.x);
        float xb = fmaf((float)(v.x >> 16),    -KQ, ga.y);
        float xc = fmaf((float)(v.y & 0xffffu), -KQ, ga.z);
        float xd = fmaf((float)(v.y >> 16),    -KQ, ga.w);
        float xe = fmaf((float)(v.z & 0xffffu), -KQ, gb.x);
        float xf = fmaf((float)(v.z >> 16),    -KQ, gb.y);
        float xg = fmaf((float)(v.w & 0xffffu), -KQ, gb.z);
        float xh = fmaf((float)(v.w >> 16),    -KQ, gb.w);
        s0 += ex2f_(xa - C); m0 = fmaxf(m0, xa);
        s1 += ex2f_(xb - C); m1 = fmaxf(m1, xb);
        s2 += ex2f_(xc - C); m2 = fmaxf(m2, xc);
        s3 += ex2f_(xd - C); m3 = fmaxf(m3, xd);
        s0 += ex2f_(xe - C); m0 = fmaxf(m0, xe);
        s1 += ex2f_(xf - C); m1 = fmaxf(m1, xf);
        s2 += ex2f_(xg - C); m2 = fmaxf(m2, xg);
        s3 += ex2f_(xh - C); m3 = fmaxf(m3, xh);
    }
    float s = (s0 + s1) + (s2 + s3);
    float m = fmaxf(fmaxf(m0, m1), fmaxf(m2, m3));
    #pragma unroll
    for (int o = 16; o; o >>= 1) {
        s += __shfl_down_sync(0xffffffffu, s, o);
        m = fmaxf(m, __shfl_down_sync(0xffffffffu, m, o));
    }
    if ((t & 31) == 0) { red_s[t >> 5] = s; red_m[t >> 5] = m; }
    __syncthreads();
    if (t < 8) {
        float stot = red_s[2 * t] + red_s[2 * t + 1];
        float mtot = fmaxf(red_m[2 * t], red_m[2 * t + 1]);
        int rr = blockIdx.x * 8 + t;
        float Cr = d_rowmax[rr] + SHIFT_MARGIN;
        float lse2 = Cr + lg2f_(stot);
        float fv = REGC * LOG_A - REG_LN2 * lse2;
        d_f[rr] = fv;
        d_fs[rr] = fv * INV_REG_LN2;
        d_rowmax[rr] = mtot;
    }
}

// SHIFTED dense g update.
__global__ void __launch_bounds__(1024) g_shift_kernel() {
    __shared__ float fs[NN];
    __shared__ float pm[32][33], ps[32][33];
    int t = threadIdx.x;
    for (int j = t; j < NN; j += 1024) fs[j] = d_fs[j];
    __syncthreads();
    int lane = t & 31;
    int rg = t >> 5;
    int col = blockIdx.x * 32 + lane;
    const unsigned short* Mc = d_Mq + col;
    float C = d_colmax[col] + SHIFT_MARGIN;
    float s0 = 0.f, s1 = 0.f, s2 = 0.f, s3 = 0.f;
    float m0 = neg_inf_(), m1 = neg_inf_(), m2 = neg_inf_(), m3 = neg_inf_();
    for (int base = 0; base < NN; base += 256) {
        int i0 = base + rg;
        unsigned short a0 = Mc[(size_t)(i0       ) * NN];
        unsigned short a1 = Mc[(size_t)(i0 + 32  ) * NN];
        unsigned short a2 = Mc[(size_t)(i0 + 64  ) * NN];
        unsigned short a3 = Mc[(size_t)(i0 + 96  ) * NN];
        unsigned short a4 = Mc[(size_t)(i0 + 128 ) * NN];
        unsigned short a5 = Mc[(size_t)(i0 + 160 ) * NN];
        unsigned short a6 = Mc[(size_t)(i0 + 192 ) * NN];
        unsigned short a7 = Mc[(size_t)(i0 + 224 ) * NN];
        float x0 = fmaf((float)a0, -KQ, fs[i0      ]);
        float x1 = fmaf((float)a1, -KQ, fs[i0 + 32 ]);
        float x2 = fmaf((float)a2, -KQ, fs[i0 + 64 ]);
        float x3 = fmaf((float)a3, -KQ, fs[i0 + 96 ]);
        float x4 = fmaf((float)a4, -KQ, fs[i0 + 128]);
        float x5 = fmaf((float)a5, -KQ, fs[i0 + 160]);
        float x6 = fmaf((float)a6, -KQ, fs[i0 + 192]);
        float x7 = fmaf((float)a7, -KQ, fs[i0 + 224]);
        s0 += ex2f_(x0 - C); m0 = fmaxf(m0, x0);
        s1 += ex2f_(x1 - C); m1 = fmaxf(m1, x1);
        s2 += ex2f_(x2 - C); m2 = fmaxf(m2, x2);
        s3 += ex2f_(x3 - C); m3 = fmaxf(m3, x3);
        s0 += ex2f_(x4 - C); m0 = fmaxf(m0, x4);
        s1 += ex2f_(x5 - C); m1 = fmaxf(m1, x5);
        s2 += ex2f_(x6 - C); m2 = fmaxf(m2, x6);
        s3 += ex2f_(x7 - C); m3 = fmaxf(m3, x7);
    }
    ps[rg][lane] = (s0 + s1) + (s2 + s3);
    pm[rg][lane] = fmaxf(fmaxf(m0, m1), fmaxf(m2, m3));
    __syncthreads();
    int w = t >> 5;
    float s2_ = ps[lane][w];
    float m2_ = pm[lane][w];
    #pragma unroll
    for (int o = 16; o; o >>= 1) {
        s2_ += __shfl_down_sync(0xffffffffu, s2_, o);
        m2_ = fmaxf(m2_, __shfl_down_sync(0xffffffffu, m2_, o));
    }
    if (lane == 0) {
        int c = blockIdx.x * 32 + w;
        float Cc = d_colmax[c] + SHIFT_MARGIN;
        float lse2 = Cc + lg2f_(s2_);
        float gv = REGC * LOG_A - REG_LN2 * lse2;
        d_g[c] = gv;
        d_gs[c] = gv * INV_REG_LN2;
        d_colmax[c] = m2_;
    }
}

// ---------------------------------------------------------------------------
// BUILD: scan Mq once; collect active entries per row and per column.
__global__ void __launch_bounds__(256) build_kernel() {
    __shared__ float gsm[NN];
    __shared__ float cth[NN];
    int t = threadIdx.x;
    for (int k = t; k < NN; k += 256) {
        gsm[k] = d_gs[k];
        cth[k] = d_colmax[k] - TH;
    }
    __syncthreads();
    int row0 = blockIdx.x * 16;
    for (int r = 0; r < 16; r++) {
        int row = row0 + r;
        float rth = d_rowmax[row] - TH;
        float fsv = d_fs[row];
        const uint4* Mr = (const uint4*)(d_Mq + (size_t)row * NN);
        for (int idx = t; idx < NN / 8; idx += 256) {
            uint4 v = Mr[idx];
            int j0 = idx * 8;
            unsigned int qs[8];
            qs[0] = v.x & 0xffffu; qs[1] = v.x >> 16;
            qs[2] = v.y & 0xffffu; qs[3] = v.y >> 16;
            qs[4] = v.z & 0xffffu; qs[5] = v.z >> 16;
            qs[6] = v.w & 0xffffu; qs[7] = v.w >> 16;
            #pragma unroll
            for (int h = 0; h < 8; h++) {
                int j = j0 + h;
                float qf = (float)qs[h];
                float xr = fmaf(qf, -KQ, gsm[j]);
                if (xr >= rth) {
                    unsigned int p = atomicAdd(&d_rowcnt[row], 1u);
                    if (p < SCAP) d_rowlist[(size_t)row * SCAP + p] = ((unsigned int)j << 16) | qs[h];
                }
                float xc = fmaf(qf, -KQ, fsv);
                if (xc >= cth[j]) {
                    unsigned int p = atomicAdd(&d_colcnt[j], 1u);
                    if (p < SCAP) d_collist[(size_t)j * SCAP + p] = ((unsigned int)row << 16) | qs[h];
                }
            }
        }
    }
}

// ---------------------------------------------------------------------------
// SPARSE Sinkhorn: cluster of 8 CTAs x 512 threads; thread-per-row/col.
// Cross-CTA data read via __ldcg (L2) — no stale-L1 hazard.
__global__ void __launch_bounds__(512) __cluster_dims__(8, 1, 1)
sparse_kernel(int npairs) {
    __shared__ float vsh[NN];
    int t = threadIdx.x;
    int id = blockIdx.x * 512 + t;

    int nr = (int)d_rowcnt[id]; if (nr > SCAP) nr = SCAP;
    int nc = (int)d_colcnt[id]; if (nc > SCAP) nc = SCAP;
    const unsigned int* rlp = d_rowlist + (size_t)id * SCAP;
    const unsigned int* clp = d_collist + (size_t)id * SCAP;

    for (int it = 0; it < npairs; it++) {
        // ---------- f pass (needs gs, L2-coherent) ----------
        for (int k = t; k < NN; k += 512) vsh[k] = __ldcg(&d_gs[k]);
        __syncthreads();
        {
            float m = neg_inf_(), s = 0.f;
            for (int k = 0; k < nr; k++) {
                unsigned int e = rlp[k];
                float x = fmaf((float)(e & 0xffffu), -KQ, vsh[e >> 16]);
                lse_accum(x, m, s);
            }
            float lse2 = m + lg2f_(s);
            float fv = REGC * LOG_A - REG_LN2 * lse2;
            d_f[id] = fv;
            d_fs[id] = fv * INV_REG_LN2;
            d_rowmax[id] = m;
        }
        __threadfence();
        __syncthreads();
        asm volatile("barrier.cluster.arrive.aligned;" ::: "memory");
        asm volatile("barrier.cluster.wait.aligned;" ::: "memory");

        // ---------- g pass (needs fs, L2-coherent) ----------
        for (int k = t; k < NN; k += 512) vsh[k] = __ldcg(&d_fs[k]);
        __syncthreads();
        {
            float m = neg_inf_(), s = 0.f;
            for (int k = 0; k < nc; k++) {
                unsigned int e = clp[k];
                float x = fmaf((float)(e & 0xffffu), -KQ, vsh[e >> 16]);
                lse_accum(x, m, s);
            }
            float lse2 = m + lg2f_(s);
            float gv = REGC * LOG_A - REG_LN2 * lse2;   // log_b == log_a
            d_g[id] = gv;
            d_gs[id] = gv * INV_REG_LN2;
            d_colmax[id] = m;
        }
        __threadfence();
        __syncthreads();
        asm volatile("barrier.cluster.arrive.aligned;" ::: "memory");
        asm volatile("barrier.cluster.wait.aligned;" ::: "memory");
    }
}

// ---------------------------------------------------------------------------
// Final reduction: S1 = sum P*M, S2 = sum P*logP, S3 = sum P (dense, exact)
__global__ void __launch_bounds__(256) final_kernel() {
    __shared__ float gsh[NN];
    __shared__ float r1[8], r2[8], r3[8];
    int t = threadIdx.x;
    for (int j = t; j < NN; j += 256) gsh[j] = d_g[j];
    __syncthreads();
    const float4* g4 = (const float4*)gsh;
    int row0 = blockIdx.x * 4;
    float S1 = 0.f, S2 = 0.f, S3 = 0.f;
    for (int r = 0; r < 4; r++) {
        float fi = d_f[row0 + r];
        const uint2* Mr = (const uint2*)(d_Mq + (size_t)(row0 + r) * NN);
        #pragma unroll
        for (int j = t; j < NN / 4; j += 256) {
            uint2 v = Mr[j];
            float4 gv = g4[j];
            float M0 = (float)(v.x & 0xffffu) * INV_QS;
            float M1 = (float)(v.x >> 16)    * INV_QS;
            float M2 = (float)(v.y & 0xffffu) * INV_QS;
            float M3 = (float)(v.y >> 16)    * INV_QS;
            float lp0 = (fi + gv.x - M0);
            float lp1 = (fi + gv.y - M1);
            float lp2 = (fi + gv.z - M2);
            float lp3 = (fi + gv.w - M3);
            float p0 = ex2f_(lp0 * INV_REG_LN2);
            float p1 = ex2f_(lp1 * INV_REG_LN2);
            float p2 = ex2f_(lp2 * INV_REG_LN2);
            float p3 = ex2f_(lp3 * INV_REG_LN2);
            S1 = fmaf(p0, M0, fmaf(p1, M1, fmaf(p2, M2, fmaf(p3, M3, S1))));
            S2 = fmaf(p0, lp0, fmaf(p1, lp1, fmaf(p2, lp2, fmaf(p3, lp3, S2))));
            S3 += (p0 + p1) + (p2 + p3);
        }
    }
    #pragma unroll
    for (int o = 16; o; o >>= 1) {
        S1 += __shfl_down_sync(0xffffffffu, S1, o);
        S2 += __shfl_down_sync(0xffffffffu, S2, o);
        S3 += __shfl_down_sync(0xffffffffu, S3, o);
    }
    if ((t & 31) == 0) { r1[t >> 5] = S1; r2[t >> 5] = S2; r3[t >> 5] = S3; }
    __syncthreads();
    if (t == 0) {
        double a1 = 0, a2 = 0, a3 = 0;
        for (int w = 0; w < 8; w++) { a1 += r1[w]; a2 += r2[w]; a3 += r3[w]; }
        atomicAdd(&d_acc[0], a1);
        atomicAdd(&d_acc[1], a2);
        atomicAdd(&d_acc[2], a3);
    }
}

__global__ void finalize_kernel(float* out) {
    double S1 = d_acc[0], S2 = d_acc[1], S3 = d_acc[2];
    double v = S1 + (double)REGC * (S2 - (double)SUM_LAB * S3 - S3 + 1.0);
    out[0] = (float)v;
}

// ---------------------------------------------------------------------------
extern "C" void kernel_launch(void* const* d_in, const int* in_sizes, int n_in,
                              void* d_out, int out_size) {
    const float* X = (const float*)d_in[0];   // source [4096,512]
    const float* Y = (const float*)d_in[1];   // target [4096,512]

    init_kernel<<<16, 256>>>();
    norms_kernel<<<2 * NN, 128>>>(X, Y);
    dim3 gg(NN / BN, NN / BM);
    gemm_kernel<<<gg, 256>>>(X, Y);

    // 12 dense pairs: 3 safe + 9 shifted
    for (int it = 0; it < SAFE_ITERS; it++) {
        f_safe_kernel<<<1024, 256>>>();
        g_safe_kernel<<<128, 1024>>>();
    }
    for (int it = 0; it < DENSE_SHIFT_ITERS; it++) {
        f_shift_kernel<<<512, 512>>>();
        g_shift_kernel<<<128, 1024>>>();
    }

    // Sparse phase: 88 pairs in 4 segments with list rebuilds
    for (int seg = 0; seg < 4; seg++) {
        zero_cnt_kernel<<<16, 256>>>();
        build_kernel<<<256, 256>>>();
        sparse_kernel<<<8, 512>>>(22);
    }

    final_kernel<<<1024, 256>>>();
    finalize_kernel<<<1, 1>>>((float*)d_out);
}